// round 12
// baseline (speedup 1.0000x reference)
#include <cuda_runtime.h>
#include <cuda_bf16.h>
#include <math.h>
#include <stdint.h>

// Problem dims (fixed by the dataset)
static constexpr int  BB  = 2;
static constexpr int  NN_ = 4096;
static constexpr int  CC  = 512;
static constexpr int  MM  = BB * NN_;               // 8192 rows total
static constexpr size_t SBATCH = (size_t)NN_ * NN_; // 16777216

// Scratch (device globals: no cudaMalloc allowed; zero-initialized)
__device__ __align__(256) unsigned short g_xh[(size_t)MM * CC];  // bf16 x hi
__device__ __align__(256) unsigned short g_xl[(size_t)MM * CC];  // bf16 x lo
__device__ __align__(256) unsigned short g_qh[(size_t)MM * CC];  // bf16 q' = x@Wqk
__device__ __align__(256) float          g_P [(size_t)MM * CC];  // fp32 P = x@W2 + bv2
__device__ __align__(256) unsigned short g_S [(size_t)BB * SBATCH]; // bf16 logits
__device__ __align__(256) unsigned short g_qkT[CC * CC];  // bf16 Wqk^T  [b][a]
__device__ __align__(256) unsigned short g_w2h[CC * CC];  // bf16 W2^T hi [j2][a]
__device__ __align__(256) unsigned short g_w2l[CC * CC];  // bf16 W2^T lo
__device__ float g_wkbq[CC];     // Wk @ bq
__device__ float g_bv2[CC];      // bv @ Wo
__device__ float g_bcol[MM];     // x @ (Wk@bq)  (column logit bias)
__device__ float g_zero[CC];     // zeros (device globals zero-init)
__device__ float g_pm[32 * MM];
__device__ float g_pl[32 * MM];
__device__ float g_cpart[32 * MM];
__device__ float g_srow[MM];

// ---------------------------------------------------------------------------
// PTX helpers (plain sm_103-compatible: mma.sync / ldmatrix / cp.async)
// ---------------------------------------------------------------------------
__device__ __forceinline__ uint32_t smem_u32(const void* p) {
    uint32_t a;
    asm("{ .reg .u64 t; cvta.to.shared.u64 t, %1; cvt.u32.u64 %0, t; }"
        : "=r"(a) : "l"(p));
    return a;
}
__device__ __forceinline__ void cp_async16(uint32_t dst, const void* src) {
    asm volatile("cp.async.cg.shared.global [%0], [%1], 16;"
                 :: "r"(dst), "l"(src) : "memory");
}
__device__ __forceinline__ void cp_commit() {
    asm volatile("cp.async.commit_group;" ::: "memory");
}
template<int N>
__device__ __forceinline__ void cp_wait() {
    asm volatile("cp.async.wait_group %0;" :: "n"(N) : "memory");
}
__device__ __forceinline__ void ldmatrix_x4(uint32_t& r0, uint32_t& r1,
                                            uint32_t& r2, uint32_t& r3,
                                            uint32_t addr) {
    asm volatile("ldmatrix.sync.aligned.m8n8.x4.shared.b16 {%0,%1,%2,%3}, [%4];"
                 : "=r"(r0), "=r"(r1), "=r"(r2), "=r"(r3) : "r"(addr));
}
__device__ __forceinline__ void mma_bf16(float& c0, float& c1, float& c2, float& c3,
                                         uint32_t a0, uint32_t a1, uint32_t a2, uint32_t a3,
                                         uint32_t b0, uint32_t b1) {
    asm volatile(
        "mma.sync.aligned.m16n8k16.row.col.f32.bf16.bf16.f32 "
        "{%0,%1,%2,%3}, {%4,%5,%6,%7}, {%8,%9}, {%0,%1,%2,%3};"
        : "+f"(c0), "+f"(c1), "+f"(c2), "+f"(c3)
        : "r"(a0), "r"(a1), "r"(a2), "r"(a3), "r"(b0), "r"(b1));
}

// smem tile layout: row-major [row][32 bf16] = 64B/row; 16B granules XOR-swizzled
__device__ __forceinline__ uint32_t sw_off(int row, int kg) {
    return (uint32_t)(row * 64 + ((kg ^ ((row >> 1) & 3)) << 4));
}

// exp via MUFU ex2.approx (1 FMA + 1 MUFU).
__device__ __forceinline__ float fexp(float x) {
    float y = x * 1.4426950408889634f;
    float r;
    asm("ex2.approx.f32 %0, %1;" : "=f"(r) : "f"(y));
    return r;
}

// ---------------------------------------------------------------------------
// K2: S[b] = q'[b] @ x[b]^T + bcol[n]. mma.sync bf16, tile 128x128, BK=32,
// 3-stage cp.async pipeline. Fused epilogue: smem-staged coalesced bf16 S
// store + per-tile softmax partials.
// ---------------------------------------------------------------------------
__global__ void __launch_bounds__(256, 2)
qk_mma_kernel(const __nv_bfloat16* __restrict__ Q,
              const __nv_bfloat16* __restrict__ Kmat,
              __nv_bfloat16* __restrict__ S,
              float* __restrict__ pm, float* __restrict__ pl,
              const float* __restrict__ bcol)
{
    __shared__ __align__(1024) char smem[3 * 16384];
    const uint32_t sbase = smem_u32(smem);

    const int tid = threadIdx.x;
    const int wid = tid >> 5;
    const int lid = tid & 31;
    const int wm  = wid & 3;
    const int wn  = wid >> 2;
    const int n0  = blockIdx.x * 128;
    const int m0  = blockIdx.y * 128;
    const int bz  = blockIdx.z;

    const __nv_bfloat16* Qb = Q    + ((size_t)bz * NN_ + m0) * CC;
    const __nv_bfloat16* Kb = Kmat + ((size_t)bz * NN_ + n0) * CC;

    const int mgrp = lid >> 3;
    const int lr   = lid & 7;
    uint32_t aoff[2][2], boff[4][2];
#pragma unroll
    for (int mt = 0; mt < 2; mt++)
#pragma unroll
        for (int kh = 0; kh < 2; kh++) {
            int row = wm * 32 + mt * 16 + lr + ((mgrp & 1) << 3);
            int kg  = 2 * kh + (mgrp >> 1);
            aoff[mt][kh] = sw_off(row, kg);
        }
#pragma unroll
    for (int i = 0; i < 4; i++)
#pragma unroll
        for (int kh = 0; kh < 2; kh++) {
            int row = wn * 64 + i * 16 + lr + ((mgrp >> 1) << 3);
            int kg  = 2 * kh + (mgrp & 1);
            boff[i][kh] = 8192u + sw_off(row, kg);
        }

    float acc[2][8][4];
#pragma unroll
    for (int mt = 0; mt < 2; mt++)
#pragma unroll
        for (int nt = 0; nt < 8; nt++)
#pragma unroll
            for (int e = 0; e < 4; e++) acc[mt][nt][e] = 0.0f;

    auto load_stage = [&](int kb, int buf) {
        uint32_t dstb = sbase + buf * 16384;
#pragma unroll
        for (int it = 0; it < 2; it++) {
            int idx = tid + it * 256;
            int row = idx >> 2, kg = idx & 3;
            cp_async16(dstb + sw_off(row, kg), Qb + (size_t)row * CC + kb * 32 + kg * 8);
        }
#pragma unroll
        for (int it = 0; it < 2; it++) {
            int idx = tid + it * 256;
            int row = idx >> 2, kg = idx & 3;
            cp_async16(dstb + 8192 + sw_off(row, kg), Kb + (size_t)row * CC + kb * 32 + kg * 8);
        }
        cp_commit();
    };

    load_stage(0, 0);
    load_stage(1, 1);

    const int KB = CC / 32;
    for (int kb = 0; kb < KB; kb++) {
        const int buf = kb % 3;
        if (kb < KB - 1) cp_wait<1>(); else cp_wait<0>();
        __syncthreads();
        if (kb + 2 < KB) load_stage(kb + 2, (kb + 2) % 3);

        const uint32_t stb = sbase + buf * 16384;
#pragma unroll
        for (int kh = 0; kh < 2; kh++) {
            uint32_t af[2][4], bf[4][4];
#pragma unroll
            for (int mt = 0; mt < 2; mt++)
                ldmatrix_x4(af[mt][0], af[mt][1], af[mt][2], af[mt][3],
                            stb + aoff[mt][kh]);
#pragma unroll
            for (int i = 0; i < 4; i++)
                ldmatrix_x4(bf[i][0], bf[i][1], bf[i][2], bf[i][3],
                            stb + boff[i][kh]);
#pragma unroll
            for (int mt = 0; mt < 2; mt++)
#pragma unroll
                for (int i = 0; i < 4; i++) {
                    mma_bf16(acc[mt][2*i][0], acc[mt][2*i][1], acc[mt][2*i][2], acc[mt][2*i][3],
                             af[mt][0], af[mt][1], af[mt][2], af[mt][3],
                             bf[i][0], bf[i][1]);
                    mma_bf16(acc[mt][2*i+1][0], acc[mt][2*i+1][1], acc[mt][2*i+1][2], acc[mt][2*i+1][3],
                             af[mt][0], af[mt][1], af[mt][2], af[mt][3],
                             bf[i][2], bf[i][3]);
                }
        }
    }

    __syncthreads();   // pipeline smem now reusable

    // Epilogue smem layout (48KB):
    //   [0, 32768): staged bf16 S tile [128][128]
    //   then s_red 256f, s_tm 128f, s_l 256f, s_bc 128f
    __nv_bfloat16* sS = (__nv_bfloat16*)smem;
    float* s_red = (float*)(smem + 32768);
    float* s_tm  = s_red + 256;
    float* s_l   = s_tm + 128;
    float* s_bc  = s_l + 256;

    if (tid < 128) s_bc[tid] = bcol[(size_t)bz * NN_ + n0 + tid];
    __syncthreads();

    const int grow = lid >> 2;
    const int gcol = (lid & 3) * 2;

    // Add column logit bias into acc (exact bias handling for bq)
#pragma unroll
    for (int mt = 0; mt < 2; mt++)
#pragma unroll
        for (int nt = 0; nt < 8; nt++) {
            const int cl = wn * 64 + nt * 8 + gcol;
            float b0 = s_bc[cl], b1 = s_bc[cl + 1];
            acc[mt][nt][0] += b0; acc[mt][nt][1] += b1;
            acc[mt][nt][2] += b0; acc[mt][nt][3] += b1;
        }

    // Sweep 1: per-thread row maxes over raw fp32 acc
    float pmax[2][2];
#pragma unroll
    for (int mt = 0; mt < 2; mt++) { pmax[mt][0] = -3.0e38f; pmax[mt][1] = -3.0e38f; }
#pragma unroll
    for (int mt = 0; mt < 2; mt++)
#pragma unroll
        for (int nt = 0; nt < 8; nt++) {
            pmax[mt][0] = fmaxf(pmax[mt][0], fmaxf(acc[mt][nt][0], acc[mt][nt][1]));
            pmax[mt][1] = fmaxf(pmax[mt][1], fmaxf(acc[mt][nt][2], acc[mt][nt][3]));
        }
#pragma unroll
    for (int mt = 0; mt < 2; mt++)
#pragma unroll
        for (int h = 0; h < 2; h++) {
            float v = pmax[mt][h];
            v = fmaxf(v, __shfl_xor_sync(0xffffffffu, v, 1));
            v = fmaxf(v, __shfl_xor_sync(0xffffffffu, v, 2));
            if ((lid & 3) == 0)
                s_red[(wm * 32 + mt * 16 + h * 8 + grow) * 2 + wn] = v;
        }
    __syncthreads();
    if (tid < 128) s_tm[tid] = fmaxf(s_red[tid * 2], s_red[tid * 2 + 1]);
    __syncthreads();

    // Sweep 2: stage bf16 S tile in smem + per-thread sumexp
    float psum[2][2] = {{0.0f, 0.0f}, {0.0f, 0.0f}};
#pragma unroll
    for (int mt = 0; mt < 2; mt++) {
        const int rl0 = wm * 32 + mt * 16 + grow;
        const float tm0 = s_tm[rl0];
        const float tm1 = s_tm[rl0 + 8];
#pragma unroll
        for (int nt = 0; nt < 8; nt++) {
            const int cl = wn * 64 + nt * 8 + gcol;
            __nv_bfloat162 h0 = __float22bfloat162_rn(
                make_float2(acc[mt][nt][0], acc[mt][nt][1]));
            __nv_bfloat162 h1 = __float22bfloat162_rn(
                make_float2(acc[mt][nt][2], acc[mt][nt][3]));
            *(__nv_bfloat162*)(sS + rl0 * 128 + cl) = h0;
            *(__nv_bfloat162*)(sS + (rl0 + 8) * 128 + cl) = h1;
            float2 f0 = __bfloat1622float2(h0);
            float2 f1 = __bfloat1622float2(h1);
            psum[mt][0] += fexp(f0.x - tm0) + fexp(f0.y - tm0);
            psum[mt][1] += fexp(f1.x - tm1) + fexp(f1.y - tm1);
        }
    }
#pragma unroll
    for (int mt = 0; mt < 2; mt++)
#pragma unroll
        for (int h = 0; h < 2; h++) {
            float v = psum[mt][h];
            v += __shfl_xor_sync(0xffffffffu, v, 1);
            v += __shfl_xor_sync(0xffffffffu, v, 2);
            if ((lid & 3) == 0)
                s_l[(wm * 32 + mt * 16 + h * 8 + grow) * 2 + wn] = v;
        }
    __syncthreads();

    // Coalesced S store: 16 consecutive threads stream one 256B row.
    {
        __nv_bfloat16* Sg = S + (size_t)bz * SBATCH + (size_t)m0 * NN_ + n0;
#pragma unroll
        for (int it = 0; it < 8; it++) {
            int c   = tid + it * 256;
            int row = c >> 4;
            int off = (c & 15) * 8;
            *(uint4*)(Sg + (size_t)row * NN_ + off) = *(uint4*)(sS + row * 128 + off);
        }
    }
    if (tid < 128) {
        const size_t brow = (size_t)bz * NN_ + m0 + tid;
        pm[(size_t)blockIdx.x * MM + brow] = s_tm[tid];
        pl[(size_t)blockIdx.x * MM + brow] = s_l[tid * 2] + s_l[tid * 2 + 1];
    }
}

// ---------------------------------------------------------------------------
// Generic mma GEMM (TERMS=1 bf16, TERMS=3 split-bf16).
// EPI 0: +bias -> bf16 out (smem-staged coalesced). EPI 1: +bias -> fp32 out.
// ---------------------------------------------------------------------------
template<int TERMS, int EPI>
__global__ void __launch_bounds__(256, 2)
mma_gemm_kernel(const __nv_bfloat16* __restrict__ Ah,
                const __nv_bfloat16* __restrict__ Al,
                const __nv_bfloat16* __restrict__ Bh,
                const __nv_bfloat16* __restrict__ Bl,
                void* __restrict__ Cout, int N, int K,
                const float* __restrict__ bias)
{
    constexpr int STAGE = (TERMS == 3) ? 32768 : 16384;
    constexpr uint32_t BOFF = (TERMS == 3) ? 16384u : 8192u;
    extern __shared__ __align__(1024) char smem[];
    const uint32_t sbase = smem_u32(smem);

    const int tid = threadIdx.x;
    const int wid = tid >> 5;
    const int lid = tid & 31;
    const int wm  = wid & 3;
    const int wn  = wid >> 2;
    const int n0  = blockIdx.x * 128;
    const int m0  = blockIdx.y * 128;

    const __nv_bfloat16* Ahb = Ah + (size_t)m0 * K;
    const __nv_bfloat16* Alb = (TERMS == 3) ? Al + (size_t)m0 * K : nullptr;
    const __nv_bfloat16* Bhb = Bh + (size_t)n0 * K;
    const __nv_bfloat16* Blb = (TERMS == 3) ? Bl + (size_t)n0 * K : nullptr;

    const int mgrp = lid >> 3;
    const int lr   = lid & 7;
    uint32_t aoff[2][2], boff[4][2];
#pragma unroll
    for (int mt = 0; mt < 2; mt++)
#pragma unroll
        for (int kh = 0; kh < 2; kh++) {
            int row = wm * 32 + mt * 16 + lr + ((mgrp & 1) << 3);
            int kg  = 2 * kh + (mgrp >> 1);
            aoff[mt][kh] = sw_off(row, kg);
        }
#pragma unroll
    for (int i = 0; i < 4; i++)
#pragma unroll
        for (int kh = 0; kh < 2; kh++) {
            int row = wn * 64 + i * 16 + lr + ((mgrp >> 1) << 3);
            int kg  = 2 * kh + (mgrp & 1);
            boff[i][kh] = BOFF + sw_off(row, kg);
        }

    float acc[2][8][4];
#pragma unroll
    for (int mt = 0; mt < 2; mt++)
#pragma unroll
        for (int nt = 0; nt < 8; nt++)
#pragma unroll
            for (int e = 0; e < 4; e++) acc[mt][nt][e] = 0.0f;

    auto load_stage = [&](int kb, int buf) {
        uint32_t dstb = sbase + buf * STAGE;
#pragma unroll
        for (int it = 0; it < 2; it++) {
            int idx = tid + it * 256;
            int row = idx >> 2, kg = idx & 3;
            size_t goff = (size_t)row * K + kb * 32 + kg * 8;
            uint32_t so = sw_off(row, kg);
            cp_async16(dstb + so, Ahb + goff);
            if (TERMS == 3) cp_async16(dstb + 8192u + so, Alb + goff);
            cp_async16(dstb + BOFF + so, Bhb + goff);
            if (TERMS == 3) cp_async16(dstb + BOFF + 8192u + so, Blb + goff);
        }
        cp_commit();
    };

    load_stage(0, 0);
    load_stage(1, 1);

    const int KB = K / 32;
    for (int kb = 0; kb < KB; kb++) {
        const int buf = kb % 3;
        if (kb < KB - 1) cp_wait<1>(); else cp_wait<0>();
        __syncthreads();
        if (kb + 2 < KB) load_stage(kb + 2, (kb + 2) % 3);

        const uint32_t stb = sbase + buf * STAGE;
#pragma unroll
        for (int kh = 0; kh < 2; kh++) {
            uint32_t afh[2][4], bfh[4][4];
            uint32_t afl[2][4], bfl[4][4];
#pragma unroll
            for (int mt = 0; mt < 2; mt++) {
                ldmatrix_x4(afh[mt][0], afh[mt][1], afh[mt][2], afh[mt][3],
                            stb + aoff[mt][kh]);
                if (TERMS == 3)
                    ldmatrix_x4(afl[mt][0], afl[mt][1], afl[mt][2], afl[mt][3],
                                stb + 8192u + aoff[mt][kh]);
            }
#pragma unroll
            for (int i = 0; i < 4; i++) {
                ldmatrix_x4(bfh[i][0], bfh[i][1], bfh[i][2], bfh[i][3],
                            stb + boff[i][kh]);
                if (TERMS == 3)
                    ldmatrix_x4(bfl[i][0], bfl[i][1], bfl[i][2], bfl[i][3],
                                stb + 8192u + boff[i][kh]);
            }
#pragma unroll
            for (int mt = 0; mt < 2; mt++)
#pragma unroll
                for (int i = 0; i < 4; i++) {
#pragma unroll
                    for (int h = 0; h < 2; h++) {
                        float* c0 = acc[mt][2*i + h];
                        mma_bf16(c0[0], c0[1], c0[2], c0[3],
                                 afh[mt][0], afh[mt][1], afh[mt][2], afh[mt][3],
                                 bfh[i][2*h], bfh[i][2*h + 1]);
                        if (TERMS == 3) {
                            mma_bf16(c0[0], c0[1], c0[2], c0[3],
                                     afh[mt][0], afh[mt][1], afh[mt][2], afh[mt][3],
                                     bfl[i][2*h], bfl[i][2*h + 1]);
                            mma_bf16(c0[0], c0[1], c0[2], c0[3],
                                     afl[mt][0], afl[mt][1], afl[mt][2], afl[mt][3],
                                     bfh[i][2*h], bfh[i][2*h + 1]);
                        }
                    }
                }
        }
    }

    const int grow = lid >> 2;
    const int gcol = (lid & 3) * 2;
    if (EPI == 0) {
        __syncthreads();
        __nv_bfloat16* sC = (__nv_bfloat16*)smem;
#pragma unroll
        for (int mt = 0; mt < 2; mt++) {
            const int rl0 = wm * 32 + mt * 16 + grow;
#pragma unroll
            for (int nt = 0; nt < 8; nt++) {
                const int cl  = wn * 64 + nt * 8 + gcol;
                const int col = n0 + cl;
                float b0 = bias[col], b1 = bias[col + 1];
                *(__nv_bfloat162*)(sC + rl0 * 128 + cl) = __float22bfloat162_rn(
                    make_float2(acc[mt][nt][0] + b0, acc[mt][nt][1] + b1));
                *(__nv_bfloat162*)(sC + (rl0 + 8) * 128 + cl) = __float22bfloat162_rn(
                    make_float2(acc[mt][nt][2] + b0, acc[mt][nt][3] + b1));
            }
        }
        __syncthreads();
        __nv_bfloat16* Cg = (__nv_bfloat16*)Cout + (size_t)m0 * N + n0;
#pragma unroll
        for (int it = 0; it < 8; it++) {
            int c   = tid + it * 256;
            int row = c >> 4;
            int off = (c & 15) * 8;
            *(uint4*)(Cg + (size_t)row * N + off) = *(uint4*)(sC + row * 128 + off);
        }
    } else {
#pragma unroll
        for (int mt = 0; mt < 2; mt++) {
#pragma unroll
            for (int nt = 0; nt < 8; nt++) {
                const int col  = n0 + wn * 64 + nt * 8 + gcol;
                const int rowa = m0 + wm * 32 + mt * 16 + grow;
                float b0 = bias[col], b1 = bias[col + 1];
                *(float2*)((float*)Cout + (size_t)rowa * N + col)
                    = make_float2(acc[mt][nt][0] + b0, acc[mt][nt][1] + b1);
                *(float2*)((float*)Cout + (size_t)(rowa + 8) * N + col)
                    = make_float2(acc[mt][nt][2] + b0, acc[mt][nt][3] + b1);
            }
        }
    }
}

// ---------------------------------------------------------------------------
// Small 512x512x512 fp32 GEMM: C[i][j] = sum_c R(i,c) * L(j,c).
// TRANSR=false: R row-major [i][c].  TRANSR=true: R accessed as R[c][i].
// Output bf16 hi (and lo if WRITE_LO), row-major [i][j].
// ---------------------------------------------------------------------------
template<bool TRANSR, bool WRITE_LO>
__global__ void __launch_bounds__(256)
smallgemm_kernel(const float* __restrict__ R, const float* __restrict__ L,
                 __nv_bfloat16* __restrict__ Ch, __nv_bfloat16* __restrict__ Cl)
{
    __shared__ float Rs[32][64];
    __shared__ float Ls[32][64];
    const int tid = threadIdx.x;
    const int i0 = blockIdx.x * 64, j0 = blockIdx.y * 64;
    const int tx = tid & 15, ty = tid >> 4;

    float acc[4][4];
#pragma unroll
    for (int a = 0; a < 4; a++)
#pragma unroll
        for (int b = 0; b < 4; b++) acc[a][b] = 0.0f;

    for (int c0 = 0; c0 < CC; c0 += 32) {
        if (!TRANSR) {
            int i = tid >> 2, cb = (tid & 3) * 8;
            float4 a = *(const float4*)(R + (size_t)(i0 + i) * CC + c0 + cb);
            float4 b = *(const float4*)(R + (size_t)(i0 + i) * CC + c0 + cb + 4);
            Rs[cb+0][i] = a.x; Rs[cb+1][i] = a.y; Rs[cb+2][i] = a.z; Rs[cb+3][i] = a.w;
            Rs[cb+4][i] = b.x; Rs[cb+5][i] = b.y; Rs[cb+6][i] = b.z; Rs[cb+7][i] = b.w;
        } else {
            int c = tid >> 3, ib = (tid & 7) * 8;
            float4 a = *(const float4*)(R + (size_t)(c0 + c) * CC + i0 + ib);
            float4 b = *(const float4*)(R + (size_t)(c0 + c) * CC + i0 + ib + 4);
            Rs[c][ib+0] = a.x; Rs[c][ib+1] = a.y; Rs[c][ib+2] = a.z; Rs[c][ib+3] = a.w;
            Rs[c][ib+4] = b.x; Rs[c][ib+5] = b.y; Rs[c][ib+6] = b.z; Rs[c][ib+7] = b.w;
        }
        {
            int j = tid >> 2, cb = (tid & 3) * 8;
            float4 a = *(const float4*)(L + (size_t)(j0 + j) * CC + c0 + cb);
            float4 b = *(const float4*)(L + (size_t)(j0 + j) * CC + c0 + cb + 4);
            Ls[cb+0][j] = a.x; Ls[cb+1][j] = a.y; Ls[cb+2][j] = a.z; Ls[cb+3][j] = a.w;
            Ls[cb+4][j] = b.x; Ls[cb+5][j] = b.y; Ls[cb+6][j] = b.z; Ls[cb+7][j] = b.w;
        }
        __syncthreads();
#pragma unroll
        for (int c = 0; c < 32; c++) {
            float ri[4], lj[4];
#pragma unroll
            for (int a = 0; a < 4; a++) ri[a] = Rs[c][ty * 4 + a];
#pragma unroll
            for (int b = 0; b < 4; b++) lj[b] = Ls[c][tx * 4 + b];
#pragma unroll
            for (int a = 0; a < 4; a++)
#pragma unroll
                for (int b = 0; b < 4; b++)
                    acc[a][b] = fmaf(ri[a], lj[b], acc[a][b]);
        }
        __syncthreads();
    }

#pragma unroll
    for (int a = 0; a < 4; a++)
#pragma unroll
        for (int b = 0; b < 4; b++) {
            size_t idx = (size_t)(i0 + ty * 4 + a) * CC + j0 + tx * 4 + b;
            float v = acc[a][b];
            __nv_bfloat16 h = __float2bfloat16(v);
            Ch[idx] = h;
            if (WRITE_LO) Cl[idx] = __float2bfloat16(v - __bfloat162float(h));
        }
}

// ---------------------------------------------------------------------------
// Vector preps: wkbq = Wk@bq (block 0), bv2 = bv@Wo (block 1).
// ---------------------------------------------------------------------------
__global__ void __launch_bounds__(512)
vec_kernel(const float* __restrict__ Wk, const float* __restrict__ bq,
           const float* __restrict__ Wo, const float* __restrict__ bv,
           float* __restrict__ wkbq, float* __restrict__ bv2)
{
    const int t = threadIdx.x;
    if (blockIdx.x == 0) {
        float acc = 0.0f;
        for (int c = 0; c < CC; c++) acc += Wk[(size_t)t * CC + c] * bq[c];
        wkbq[t] = acc;
    } else {
        float acc = 0.0f;
        for (int c = 0; c < CC; c++) acc += bv[c] * Wo[(size_t)c * CC + t];
        bv2[t] = acc;
    }
}

// bcol[r] = x_r . wkbq  (warp per row)
__global__ void __launch_bounds__(256)
bcol_kernel(const float* __restrict__ x, const float* __restrict__ wkbq,
            float* __restrict__ bcol)
{
    __shared__ float w[CC];
    for (int i = threadIdx.x; i < CC; i += 256) w[i] = wkbq[i];
    __syncthreads();
    const int warp = threadIdx.x >> 5, lane = threadIdx.x & 31;
    const int r = blockIdx.x * 8 + warp;
    const float* xr = x + (size_t)r * CC;
    float acc = 0.0f;
#pragma unroll
    for (int c = lane * 4; c < CC; c += 128) {
        float4 v = *(const float4*)(xr + c);
        acc += v.x * w[c] + v.y * w[c+1] + v.z * w[c+2] + v.w * w[c+3];
    }
#pragma unroll
    for (int o = 16; o > 0; o >>= 1) acc += __shfl_xor_sync(0xffffffffu, acc, o);
    if (lane == 0) bcol[r] = acc;
}

// split fp32 -> bf16 hi/lo
__global__ void __launch_bounds__(256)
split_kernel(const float* __restrict__ x,
             __nv_bfloat16* __restrict__ xh, __nv_bfloat16* __restrict__ xl)
{
    size_t i = ((size_t)blockIdx.x * 256 + threadIdx.x) * 4;
    float4 v = *(const float4*)(x + i);
    __nv_bfloat16 h0 = __float2bfloat16(v.x), h1 = __float2bfloat16(v.y);
    __nv_bfloat16 h2 = __float2bfloat16(v.z), h3 = __float2bfloat16(v.w);
    __nv_bfloat16 l0 = __float2bfloat16(v.x - __bfloat162float(h0));
    __nv_bfloat16 l1 = __float2bfloat16(v.y - __bfloat162float(h1));
    __nv_bfloat16 l2 = __float2bfloat16(v.z - __bfloat162float(h2));
    __nv_bfloat16 l3 = __float2bfloat16(v.w - __bfloat162float(h3));
    __nv_bfloat162 hp[2] = {{h0, h1}, {h2, h3}};
    __nv_bfloat162 lp[2] = {{l0, l1}, {l2, l3}};
    *(uint2*)(xh + i) = *(uint2*)hp;
    *(uint2*)(xl + i) = *(uint2*)lp;
}

// ---------------------------------------------------------------------------
// Column sums of normalized attention (bf16 S), 32-way m-split, 4 cols/thread.
// Fused combine: each block derives rowm/rowinvl for its 128 rows from pm/pl.
// ---------------------------------------------------------------------------
__global__ void __launch_bounds__(256)
colsum_part_kernel(const __nv_bfloat16* __restrict__ S,
                   const float* __restrict__ pm,
                   const float* __restrict__ pl,
                   float* __restrict__ cpart)
{
    __shared__ float sm[128], si[128];
    const int b     = blockIdx.z;
    const int n     = blockIdx.x * 1024 + threadIdx.x * 4;
    const int m0    = blockIdx.y * 128;
    const int rbase = b * 4096;
    if (threadIdx.x < 128) {
        const int r = rbase + m0 + threadIdx.x;
        float M = -3.0e38f;
#pragma unroll
        for (int t = 0; t < 32; t++) M = fmaxf(M, pm[(size_t)t * MM + r]);
        float L = 0.0f;
#pragma unroll
        for (int t = 0; t < 32; t++)
            L += pl[(size_t)t * MM + r] * fexp(pm[(size_t)t * MM + r] - M);
        sm[threadIdx.x] = M;
        si[threadIdx.x] = 1.0f / L;
    }
    __syncthreads();
    const __nv_bfloat16* Sb = S + (size_t)b * SBATCH + (size_t)m0 * 4096 + n;
    float a0 = 0.0f, a1 = 0.0f, a2 = 0.0f, a3 = 0.0f;
#pragma unroll 4
    for (int mm = 0; mm < 128; mm++) {
        uint2 u = *(const uint2*)(Sb + (size_t)mm * 4096);
        float2 f0 = __bfloat1622float2(reinterpret_cast<__nv_bfloat162&>(u.x));
        float2 f1 = __bfloat1622float2(reinterpret_cast<__nv_bfloat162&>(u.y));
        float m = sm[mm], iv = si[mm];
        a0 += fexp(f0.x - m) * iv;
        a1 += fexp(f0.y - m) * iv;
        a2 += fexp(f1.x - m) * iv;
        a3 += fexp(f1.y - m) * iv;
    }
    *(float4*)(cpart + (size_t)blockIdx.y * MM + rbase + n)
        = make_float4(a0, a1, a2, a3);
}

__global__ void __launch_bounds__(256)
colsum_final_kernel(const float* __restrict__ cpart, float* __restrict__ srow)
{
    const int i = blockIdx.x * 256 + threadIdx.x;
    float c = 0.0f;
#pragma unroll
    for (int p = 0; p < 32; p++) c += cpart[(size_t)p * MM + i];
    srow[i] = c / (c + 1e-9f);
}

// ---------------------------------------------------------------------------
// Final elementwise epilogue: out = relu(BN(s[r]*P + bo)) + x
// ---------------------------------------------------------------------------
__global__ void __launch_bounds__(256)
final_epi_kernel(const float* __restrict__ P, const float* __restrict__ srow,
                 const float* __restrict__ x, const float* __restrict__ bo,
                 const float* __restrict__ bns, const float* __restrict__ bnb,
                 const float* __restrict__ bnm, const float* __restrict__ bnv,
                 float* __restrict__ out)
{
    size_t i = ((size_t)blockIdx.x * 256 + threadIdx.x) * 4;
    const int r = (int)(i >> 9);
    const int c = (int)(i & 511);
    const float s = srow[r];
    float4 p = *(const float4*)(P + i);
    float4 xr = *(const float4*)(x + i);
    float pv[4] = {p.x, p.y, p.z, p.w};
    float xv[4] = {xr.x, xr.y, xr.z, xr.w};
    float o[4];
#pragma unroll
    for (int j = 0; j < 4; j++) {
        const int cc = c + j;
        float g = rsqrtf(bnv[cc] + 1e-5f) * bns[cc];
        float v = s * pv[j] + bo[cc];
        v = (v - bnm[cc]) * g + bnb[cc];
        o[j] = fmaxf(v, 0.0f) + xv[j];
    }
    *(float4*)(out + i) = make_float4(o[0], o[1], o[2], o[3]);
}

// ---------------------------------------------------------------------------
extern "C" void kernel_launch(void* const* d_in, const int* in_sizes, int n_in,
                              void* d_out, int out_size)
{
    // metadata order: inputs, Wq, Wk, Wv, Wo, bq, bk, bv, bo, bn_* (two loops!)
    const float* x   = (const float*)d_in[0];
    const float* Wq  = (const float*)d_in[1];
    const float* Wk  = (const float*)d_in[2];
    const float* Wv  = (const float*)d_in[3];
    const float* Wo  = (const float*)d_in[4];
    const float* bq  = (const float*)d_in[5];
    // bk (d_in[6]) only contributes row-constant logit terms -> cancels in softmax.
    const float* bv  = (const float*)d_in[7];
    const float* bo  = (const float*)d_in[8];
    const float* bns = (const float*)d_in[9];
    const float* bnb = (const float*)d_in[10];
    const float* bnm = (const float*)d_in[11];
    const float* bnv = (const float*)d_in[12];
    float* out = (float*)d_out;

    void *xh, *xl, *qh, *P, *S, *qkT, *w2h, *w2l;
    void *wkbq, *bv2, *bcol, *zero, *pm, *pl, *cpart, *srow;
    cudaGetSymbolAddress(&xh,   g_xh);   cudaGetSymbolAddress(&xl,   g_xl);
    cudaGetSymbolAddress(&qh,   g_qh);   cudaGetSymbolAddress(&P,    g_P);
    cudaGetSymbolAddress(&S,    g_S);
    cudaGetSymbolAddress(&qkT,  g_qkT);
    cudaGetSymbolAddress(&w2h,  g_w2h);  cudaGetSymbolAddress(&w2l,  g_w2l);
    cudaGetSymbolAddress(&wkbq, g_wkbq); cudaGetSymbolAddress(&bv2,  g_bv2);
    cudaGetSymbolAddress(&bcol, g_bcol); cudaGetSymbolAddress(&zero, g_zero);
    cudaGetSymbolAddress(&pm,    g_pm);
    cudaGetSymbolAddress(&pl,    g_pl);
    cudaGetSymbolAddress(&cpart, g_cpart);
    cudaGetSymbolAddress(&srow,  g_srow);

    static cudaStream_t s2 = nullptr;
    static cudaEvent_t  eFork = nullptr, eQk = nullptr, eP = nullptr;
    if (s2 == nullptr) {
        cudaStreamCreateWithFlags(&s2, cudaStreamNonBlocking);
        cudaEventCreateWithFlags(&eFork, cudaEventDisableTiming);
        cudaEventCreateWithFlags(&eQk, cudaEventDisableTiming);
        cudaEventCreateWithFlags(&eP, cudaEventDisableTiming);
        cudaFuncSetAttribute(mma_gemm_kernel<1, 0>,
            cudaFuncAttributeMaxDynamicSharedMemorySize, 49152);
        cudaFuncSetAttribute(mma_gemm_kernel<3, 1>,
            cudaFuncAttributeMaxDynamicSharedMemorySize, 98304);
    }

    dim3 blk(256);
    dim3 gProj(CC / 128, MM / 128);           // (4, 64)

    // main: split x into bf16 hi/lo; fork s2 AFTER an event recorded in the
    // capturing stream (required for graph capture to absorb s2's work).
    split_kernel<<<(MM * CC) / 1024, blk>>>(x, (__nv_bfloat16*)xh, (__nv_bfloat16*)xl);
    cudaEventRecord(eFork, 0);
    cudaStreamWaitEvent(s2, eFork, 0);

    // s2: vector preps + small weight GEMMs + P GEMM (off critical path)
    vec_kernel<<<2, 512, 0, s2>>>(Wk, bq, Wo, bv, (float*)wkbq, (float*)bv2);
    bcol_kernel<<<MM / 8, blk, 0, s2>>>(x, (const float*)wkbq, (float*)bcol);
    // Wqk^T[b][a] = sum_c Wk[b,c] * Wq[a,c]
    smallgemm_kernel<false, false><<<dim3(8, 8), blk, 0, s2>>>(
        Wk, Wq, (__nv_bfloat16*)qkT, nullptr);
    cudaEventRecord(eQk, s2);
    // W2^T[j2][a] = sum_c Wo[c,j2] * Wv[a,c]   (hi + lo)
    smallgemm_kernel<true, true><<<dim3(8, 8), blk, 0, s2>>>(
        Wo, Wv, (__nv_bfloat16*)w2h, (__nv_bfloat16*)w2l);
    // P = x @ W2 + bv2 (split-bf16, fp32 out)
    mma_gemm_kernel<3, 1><<<gProj, blk, 98304, s2>>>(
        (const __nv_bfloat16*)xh, (const __nv_bfloat16*)xl,
        (const __nv_bfloat16*)w2h, (const __nv_bfloat16*)w2l,
        P, CC, CC, (const float*)bv2);
    cudaEventRecord(eP, s2);

    // main: q' = x @ Wqk (needs qkT + bcol from s2, both done by eQk)
    cudaStreamWaitEvent(0, eQk, 0);
    mma_gemm_kernel<1, 0><<<gProj, blk, 49152>>>(
        (const __nv_bfloat16*)xh, nullptr, (const __nv_bfloat16*)qkT, nullptr,
        qh, CC, CC, (const float*)zero);

    // K2: S = q' @ x^T + bcol, fused per-tile softmax stats
    qk_mma_kernel<<<dim3(32, 32, 2), blk>>>(
        (const __nv_bfloat16*)qh, (const __nv_bfloat16*)xh, (__nv_bfloat16*)S,
        (float*)pm, (float*)pl, (const float*)bcol);

    // colsum -> s[n]
    colsum_part_kernel<<<dim3(4, 32, 2), blk>>>((const __nv_bfloat16*)S,
        (const float*)pm, (const float*)pl, (float*)cpart);
    colsum_final_kernel<<<MM / 256, blk>>>((const float*)cpart, (float*)srow);

    // final: out = relu(BN(s[r]*P + bo)) + x   (needs P from s2)
    cudaStreamWaitEvent(0, eP, 0);
    final_epi_kernel<<<(MM * CC) / 1024, blk>>>(
        (const float*)P, (const float*)srow, x, bo, bns, bnb, bnm, bnv, out);
}

// round 13
// speedup vs baseline: 1.5625x; 1.5625x over previous
#include <cuda_runtime.h>
#include <cuda_bf16.h>
#include <math.h>
#include <stdint.h>

// Problem dims (fixed by the dataset)
static constexpr int  BB  = 2;
static constexpr int  NN_ = 4096;
static constexpr int  CC  = 512;
static constexpr int  MM  = BB * NN_;               // 8192 rows total
static constexpr size_t SBATCH = (size_t)NN_ * NN_; // 16777216

// Scratch (device globals: no cudaMalloc allowed; zero-initialized)
__device__ __align__(256) unsigned short g_xh[(size_t)MM * CC];  // bf16 x hi
__device__ __align__(256) unsigned short g_xl[(size_t)MM * CC];  // bf16 x lo
__device__ __align__(256) unsigned short g_qh[(size_t)MM * CC];  // bf16 q' = x@Wqk
__device__ __align__(256) float          g_P [(size_t)MM * CC];  // fp32 P = x@W2 + bv2
__device__ __align__(256) unsigned short g_S [(size_t)BB * SBATCH]; // bf16 logits
__device__ __align__(256) unsigned short g_qkT[CC * CC];  // bf16 Wqk^T  [b][a]
__device__ __align__(256) unsigned short g_w2h[CC * CC];  // bf16 W2^T hi [j2][a]
__device__ __align__(256) unsigned short g_w2l[CC * CC];  // bf16 W2^T lo
__device__ __align__(256) float g_part1[8 * CC * CC];     // k-split partials (qkT)
__device__ __align__(256) float g_part2[8 * CC * CC];     // k-split partials (w2)
__device__ float g_wkbq[CC];     // Wk @ bq
__device__ float g_bv2[CC];      // bv @ Wo
__device__ float g_bcol[MM];     // x @ (Wk@bq)  (column logit bias)
__device__ float g_zero[CC];     // zeros (device globals zero-init)
__device__ float g_pm[32 * MM];
__device__ float g_pl[32 * MM];
__device__ float g_cpart[32 * MM];
__device__ float g_srow[MM];

// ---------------------------------------------------------------------------
// PTX helpers (plain sm_103-compatible: mma.sync / ldmatrix / cp.async)
// ---------------------------------------------------------------------------
__device__ __forceinline__ uint32_t smem_u32(const void* p) {
    uint32_t a;
    asm("{ .reg .u64 t; cvta.to.shared.u64 t, %1; cvt.u32.u64 %0, t; }"
        : "=r"(a) : "l"(p));
    return a;
}
__device__ __forceinline__ void cp_async16(uint32_t dst, const void* src) {
    asm volatile("cp.async.cg.shared.global [%0], [%1], 16;"
                 :: "r"(dst), "l"(src) : "memory");
}
__device__ __forceinline__ void cp_commit() {
    asm volatile("cp.async.commit_group;" ::: "memory");
}
template<int N>
__device__ __forceinline__ void cp_wait() {
    asm volatile("cp.async.wait_group %0;" :: "n"(N) : "memory");
}
__device__ __forceinline__ void ldmatrix_x4(uint32_t& r0, uint32_t& r1,
                                            uint32_t& r2, uint32_t& r3,
                                            uint32_t addr) {
    asm volatile("ldmatrix.sync.aligned.m8n8.x4.shared.b16 {%0,%1,%2,%3}, [%4];"
                 : "=r"(r0), "=r"(r1), "=r"(r2), "=r"(r3) : "r"(addr));
}
__device__ __forceinline__ void mma_bf16(float& c0, float& c1, float& c2, float& c3,
                                         uint32_t a0, uint32_t a1, uint32_t a2, uint32_t a3,
                                         uint32_t b0, uint32_t b1) {
    asm volatile(
        "mma.sync.aligned.m16n8k16.row.col.f32.bf16.bf16.f32 "
        "{%0,%1,%2,%3}, {%4,%5,%6,%7}, {%8,%9}, {%0,%1,%2,%3};"
        : "+f"(c0), "+f"(c1), "+f"(c2), "+f"(c3)
        : "r"(a0), "r"(a1), "r"(a2), "r"(a3), "r"(b0), "r"(b1));
}

// smem tile layout: row-major [row][32 bf16] = 64B/row; 16B granules XOR-swizzled
__device__ __forceinline__ uint32_t sw_off(int row, int kg) {
    return (uint32_t)(row * 64 + ((kg ^ ((row >> 1) & 3)) << 4));
}

// exp via MUFU ex2.approx (1 FMA + 1 MUFU).
__device__ __forceinline__ float fexp(float x) {
    float y = x * 1.4426950408889634f;
    float r;
    asm("ex2.approx.f32 %0, %1;" : "=f"(r) : "f"(y));
    return r;
}

// ---------------------------------------------------------------------------
// K2: S[b] = q'[b] @ x[b]^T + bcol[n]. mma.sync bf16, tile 128x128, BK=32,
// 3-stage cp.async pipeline. Fused epilogue: smem-staged coalesced bf16 S
// store + per-tile softmax partials.
// ---------------------------------------------------------------------------
__global__ void __launch_bounds__(256, 2)
qk_mma_kernel(const __nv_bfloat16* __restrict__ Q,
              const __nv_bfloat16* __restrict__ Kmat,
              __nv_bfloat16* __restrict__ S,
              float* __restrict__ pm, float* __restrict__ pl,
              const float* __restrict__ bcol)
{
    __shared__ __align__(1024) char smem[3 * 16384];
    const uint32_t sbase = smem_u32(smem);

    const int tid = threadIdx.x;
    const int wid = tid >> 5;
    const int lid = tid & 31;
    const int wm  = wid & 3;
    const int wn  = wid >> 2;
    const int n0  = blockIdx.x * 128;
    const int m0  = blockIdx.y * 128;
    const int bz  = blockIdx.z;

    const __nv_bfloat16* Qb = Q    + ((size_t)bz * NN_ + m0) * CC;
    const __nv_bfloat16* Kb = Kmat + ((size_t)bz * NN_ + n0) * CC;

    const int mgrp = lid >> 3;
    const int lr   = lid & 7;
    uint32_t aoff[2][2], boff[4][2];
#pragma unroll
    for (int mt = 0; mt < 2; mt++)
#pragma unroll
        for (int kh = 0; kh < 2; kh++) {
            int row = wm * 32 + mt * 16 + lr + ((mgrp & 1) << 3);
            int kg  = 2 * kh + (mgrp >> 1);
            aoff[mt][kh] = sw_off(row, kg);
        }
#pragma unroll
    for (int i = 0; i < 4; i++)
#pragma unroll
        for (int kh = 0; kh < 2; kh++) {
            int row = wn * 64 + i * 16 + lr + ((mgrp >> 1) << 3);
            int kg  = 2 * kh + (mgrp & 1);
            boff[i][kh] = 8192u + sw_off(row, kg);
        }

    float acc[2][8][4];
#pragma unroll
    for (int mt = 0; mt < 2; mt++)
#pragma unroll
        for (int nt = 0; nt < 8; nt++)
#pragma unroll
            for (int e = 0; e < 4; e++) acc[mt][nt][e] = 0.0f;

    auto load_stage = [&](int kb, int buf) {
        uint32_t dstb = sbase + buf * 16384;
#pragma unroll
        for (int it = 0; it < 2; it++) {
            int idx = tid + it * 256;
            int row = idx >> 2, kg = idx & 3;
            cp_async16(dstb + sw_off(row, kg), Qb + (size_t)row * CC + kb * 32 + kg * 8);
        }
#pragma unroll
        for (int it = 0; it < 2; it++) {
            int idx = tid + it * 256;
            int row = idx >> 2, kg = idx & 3;
            cp_async16(dstb + 8192 + sw_off(row, kg), Kb + (size_t)row * CC + kb * 32 + kg * 8);
        }
        cp_commit();
    };

    load_stage(0, 0);
    load_stage(1, 1);

    const int KB = CC / 32;
    for (int kb = 0; kb < KB; kb++) {
        const int buf = kb % 3;
        if (kb < KB - 1) cp_wait<1>(); else cp_wait<0>();
        __syncthreads();
        if (kb + 2 < KB) load_stage(kb + 2, (kb + 2) % 3);

        const uint32_t stb = sbase + buf * 16384;
#pragma unroll
        for (int kh = 0; kh < 2; kh++) {
            uint32_t af[2][4], bf[4][4];
#pragma unroll
            for (int mt = 0; mt < 2; mt++)
                ldmatrix_x4(af[mt][0], af[mt][1], af[mt][2], af[mt][3],
                            stb + aoff[mt][kh]);
#pragma unroll
            for (int i = 0; i < 4; i++)
                ldmatrix_x4(bf[i][0], bf[i][1], bf[i][2], bf[i][3],
                            stb + boff[i][kh]);
#pragma unroll
            for (int mt = 0; mt < 2; mt++)
#pragma unroll
                for (int i = 0; i < 4; i++) {
                    mma_bf16(acc[mt][2*i][0], acc[mt][2*i][1], acc[mt][2*i][2], acc[mt][2*i][3],
                             af[mt][0], af[mt][1], af[mt][2], af[mt][3],
                             bf[i][0], bf[i][1]);
                    mma_bf16(acc[mt][2*i+1][0], acc[mt][2*i+1][1], acc[mt][2*i+1][2], acc[mt][2*i+1][3],
                             af[mt][0], af[mt][1], af[mt][2], af[mt][3],
                             bf[i][2], bf[i][3]);
                }
        }
    }

    __syncthreads();   // pipeline smem now reusable

    __nv_bfloat16* sS = (__nv_bfloat16*)smem;
    float* s_red = (float*)(smem + 32768);
    float* s_tm  = s_red + 256;
    float* s_l   = s_tm + 128;
    float* s_bc  = s_l + 256;

    if (tid < 128) s_bc[tid] = bcol[(size_t)bz * NN_ + n0 + tid];
    __syncthreads();

    const int grow = lid >> 2;
    const int gcol = (lid & 3) * 2;

    // Add column logit bias into acc (exact bias handling for bq)
#pragma unroll
    for (int mt = 0; mt < 2; mt++)
#pragma unroll
        for (int nt = 0; nt < 8; nt++) {
            const int cl = wn * 64 + nt * 8 + gcol;
            float b0 = s_bc[cl], b1 = s_bc[cl + 1];
            acc[mt][nt][0] += b0; acc[mt][nt][1] += b1;
            acc[mt][nt][2] += b0; acc[mt][nt][3] += b1;
        }

    // Sweep 1: per-thread row maxes over raw fp32 acc
    float pmax[2][2];
#pragma unroll
    for (int mt = 0; mt < 2; mt++) { pmax[mt][0] = -3.0e38f; pmax[mt][1] = -3.0e38f; }
#pragma unroll
    for (int mt = 0; mt < 2; mt++)
#pragma unroll
        for (int nt = 0; nt < 8; nt++) {
            pmax[mt][0] = fmaxf(pmax[mt][0], fmaxf(acc[mt][nt][0], acc[mt][nt][1]));
            pmax[mt][1] = fmaxf(pmax[mt][1], fmaxf(acc[mt][nt][2], acc[mt][nt][3]));
        }
#pragma unroll
    for (int mt = 0; mt < 2; mt++)
#pragma unroll
        for (int h = 0; h < 2; h++) {
            float v = pmax[mt][h];
            v = fmaxf(v, __shfl_xor_sync(0xffffffffu, v, 1));
            v = fmaxf(v, __shfl_xor_sync(0xffffffffu, v, 2));
            if ((lid & 3) == 0)
                s_red[(wm * 32 + mt * 16 + h * 8 + grow) * 2 + wn] = v;
        }
    __syncthreads();
    if (tid < 128) s_tm[tid] = fmaxf(s_red[tid * 2], s_red[tid * 2 + 1]);
    __syncthreads();

    // Sweep 2: stage bf16 S tile in smem + per-thread sumexp
    float psum[2][2] = {{0.0f, 0.0f}, {0.0f, 0.0f}};
#pragma unroll
    for (int mt = 0; mt < 2; mt++) {
        const int rl0 = wm * 32 + mt * 16 + grow;
        const float tm0 = s_tm[rl0];
        const float tm1 = s_tm[rl0 + 8];
#pragma unroll
        for (int nt = 0; nt < 8; nt++) {
            const int cl = wn * 64 + nt * 8 + gcol;
            __nv_bfloat162 h0 = __float22bfloat162_rn(
                make_float2(acc[mt][nt][0], acc[mt][nt][1]));
            __nv_bfloat162 h1 = __float22bfloat162_rn(
                make_float2(acc[mt][nt][2], acc[mt][nt][3]));
            *(__nv_bfloat162*)(sS + rl0 * 128 + cl) = h0;
            *(__nv_bfloat162*)(sS + (rl0 + 8) * 128 + cl) = h1;
            float2 f0 = __bfloat1622float2(h0);
            float2 f1 = __bfloat1622float2(h1);
            psum[mt][0] += fexp(f0.x - tm0) + fexp(f0.y - tm0);
            psum[mt][1] += fexp(f1.x - tm1) + fexp(f1.y - tm1);
        }
    }
#pragma unroll
    for (int mt = 0; mt < 2; mt++)
#pragma unroll
        for (int h = 0; h < 2; h++) {
            float v = psum[mt][h];
            v += __shfl_xor_sync(0xffffffffu, v, 1);
            v += __shfl_xor_sync(0xffffffffu, v, 2);
            if ((lid & 3) == 0)
                s_l[(wm * 32 + mt * 16 + h * 8 + grow) * 2 + wn] = v;
        }
    __syncthreads();

    // Coalesced S store
    {
        __nv_bfloat16* Sg = S + (size_t)bz * SBATCH + (size_t)m0 * NN_ + n0;
#pragma unroll
        for (int it = 0; it < 8; it++) {
            int c   = tid + it * 256;
            int row = c >> 4;
            int off = (c & 15) * 8;
            *(uint4*)(Sg + (size_t)row * NN_ + off) = *(uint4*)(sS + row * 128 + off);
        }
    }
    if (tid < 128) {
        const size_t brow = (size_t)bz * NN_ + m0 + tid;
        pm[(size_t)blockIdx.x * MM + brow] = s_tm[tid];
        pl[(size_t)blockIdx.x * MM + brow] = s_l[tid * 2] + s_l[tid * 2 + 1];
    }
}

// ---------------------------------------------------------------------------
// Generic mma GEMM (TERMS=1 bf16, TERMS=3 split-bf16).
// EPI 0: +bias -> bf16 out (smem-staged coalesced). EPI 1: +bias -> fp32 out.
// ---------------------------------------------------------------------------
template<int TERMS, int EPI>
__global__ void __launch_bounds__(256, 2)
mma_gemm_kernel(const __nv_bfloat16* __restrict__ Ah,
                const __nv_bfloat16* __restrict__ Al,
                const __nv_bfloat16* __restrict__ Bh,
                const __nv_bfloat16* __restrict__ Bl,
                void* __restrict__ Cout, int N, int K,
                const float* __restrict__ bias)
{
    constexpr int STAGE = (TERMS == 3) ? 32768 : 16384;
    constexpr uint32_t BOFF = (TERMS == 3) ? 16384u : 8192u;
    extern __shared__ __align__(1024) char smem[];
    const uint32_t sbase = smem_u32(smem);

    const int tid = threadIdx.x;
    const int wid = tid >> 5;
    const int lid = tid & 31;
    const int wm  = wid & 3;
    const int wn  = wid >> 2;
    const int n0  = blockIdx.x * 128;
    const int m0  = blockIdx.y * 128;

    const __nv_bfloat16* Ahb = Ah + (size_t)m0 * K;
    const __nv_bfloat16* Alb = (TERMS == 3) ? Al + (size_t)m0 * K : nullptr;
    const __nv_bfloat16* Bhb = Bh + (size_t)n0 * K;
    const __nv_bfloat16* Blb = (TERMS == 3) ? Bl + (size_t)n0 * K : nullptr;

    const int mgrp = lid >> 3;
    const int lr   = lid & 7;
    uint32_t aoff[2][2], boff[4][2];
#pragma unroll
    for (int mt = 0; mt < 2; mt++)
#pragma unroll
        for (int kh = 0; kh < 2; kh++) {
            int row = wm * 32 + mt * 16 + lr + ((mgrp & 1) << 3);
            int kg  = 2 * kh + (mgrp >> 1);
            aoff[mt][kh] = sw_off(row, kg);
        }
#pragma unroll
    for (int i = 0; i < 4; i++)
#pragma unroll
        for (int kh = 0; kh < 2; kh++) {
            int row = wn * 64 + i * 16 + lr + ((mgrp >> 1) << 3);
            int kg  = 2 * kh + (mgrp & 1);
            boff[i][kh] = BOFF + sw_off(row, kg);
        }

    float acc[2][8][4];
#pragma unroll
    for (int mt = 0; mt < 2; mt++)
#pragma unroll
        for (int nt = 0; nt < 8; nt++)
#pragma unroll
            for (int e = 0; e < 4; e++) acc[mt][nt][e] = 0.0f;

    auto load_stage = [&](int kb, int buf) {
        uint32_t dstb = sbase + buf * STAGE;
#pragma unroll
        for (int it = 0; it < 2; it++) {
            int idx = tid + it * 256;
            int row = idx >> 2, kg = idx & 3;
            size_t goff = (size_t)row * K + kb * 32 + kg * 8;
            uint32_t so = sw_off(row, kg);
            cp_async16(dstb + so, Ahb + goff);
            if (TERMS == 3) cp_async16(dstb + 8192u + so, Alb + goff);
            cp_async16(dstb + BOFF + so, Bhb + goff);
            if (TERMS == 3) cp_async16(dstb + BOFF + 8192u + so, Blb + goff);
        }
        cp_commit();
    };

    load_stage(0, 0);
    load_stage(1, 1);

    const int KB = K / 32;
    for (int kb = 0; kb < KB; kb++) {
        const int buf = kb % 3;
        if (kb < KB - 1) cp_wait<1>(); else cp_wait<0>();
        __syncthreads();
        if (kb + 2 < KB) load_stage(kb + 2, (kb + 2) % 3);

        const uint32_t stb = sbase + buf * STAGE;
#pragma unroll
        for (int kh = 0; kh < 2; kh++) {
            uint32_t afh[2][4], bfh[4][4];
            uint32_t afl[2][4], bfl[4][4];
#pragma unroll
            for (int mt = 0; mt < 2; mt++) {
                ldmatrix_x4(afh[mt][0], afh[mt][1], afh[mt][2], afh[mt][3],
                            stb + aoff[mt][kh]);
                if (TERMS == 3)
                    ldmatrix_x4(afl[mt][0], afl[mt][1], afl[mt][2], afl[mt][3],
                                stb + 8192u + aoff[mt][kh]);
            }
#pragma unroll
            for (int i = 0; i < 4; i++) {
                ldmatrix_x4(bfh[i][0], bfh[i][1], bfh[i][2], bfh[i][3],
                            stb + boff[i][kh]);
                if (TERMS == 3)
                    ldmatrix_x4(bfl[i][0], bfl[i][1], bfl[i][2], bfl[i][3],
                                stb + 8192u + boff[i][kh]);
            }
#pragma unroll
            for (int mt = 0; mt < 2; mt++)
#pragma unroll
                for (int i = 0; i < 4; i++) {
#pragma unroll
                    for (int h = 0; h < 2; h++) {
                        float* c0 = acc[mt][2*i + h];
                        mma_bf16(c0[0], c0[1], c0[2], c0[3],
                                 afh[mt][0], afh[mt][1], afh[mt][2], afh[mt][3],
                                 bfh[i][2*h], bfh[i][2*h + 1]);
                        if (TERMS == 3) {
                            mma_bf16(c0[0], c0[1], c0[2], c0[3],
                                     afh[mt][0], afh[mt][1], afh[mt][2], afh[mt][3],
                                     bfl[i][2*h], bfl[i][2*h + 1]);
                            mma_bf16(c0[0], c0[1], c0[2], c0[3],
                                     afl[mt][0], afl[mt][1], afl[mt][2], afl[mt][3],
                                     bfh[i][2*h], bfh[i][2*h + 1]);
                        }
                    }
                }
        }
    }

    const int grow = lid >> 2;
    const int gcol = (lid & 3) * 2;
    if (EPI == 0) {
        __syncthreads();
        __nv_bfloat16* sC = (__nv_bfloat16*)smem;
#pragma unroll
        for (int mt = 0; mt < 2; mt++) {
            const int rl0 = wm * 32 + mt * 16 + grow;
#pragma unroll
            for (int nt = 0; nt < 8; nt++) {
                const int cl  = wn * 64 + nt * 8 + gcol;
                const int col = n0 + cl;
                float b0 = bias[col], b1 = bias[col + 1];
                *(__nv_bfloat162*)(sC + rl0 * 128 + cl) = __float22bfloat162_rn(
                    make_float2(acc[mt][nt][0] + b0, acc[mt][nt][1] + b1));
                *(__nv_bfloat162*)(sC + (rl0 + 8) * 128 + cl) = __float22bfloat162_rn(
                    make_float2(acc[mt][nt][2] + b0, acc[mt][nt][3] + b1));
            }
        }
        __syncthreads();
        __nv_bfloat16* Cg = (__nv_bfloat16*)Cout + (size_t)m0 * N + n0;
#pragma unroll
        for (int it = 0; it < 8; it++) {
            int c   = tid + it * 256;
            int row = c >> 4;
            int off = (c & 15) * 8;
            *(uint4*)(Cg + (size_t)row * N + off) = *(uint4*)(sC + row * 128 + off);
        }
    } else {
#pragma unroll
        for (int mt = 0; mt < 2; mt++) {
#pragma unroll
            for (int nt = 0; nt < 8; nt++) {
                const int col  = n0 + wn * 64 + nt * 8 + gcol;
                const int rowa = m0 + wm * 32 + mt * 16 + grow;
                float b0 = bias[col], b1 = bias[col + 1];
                *(float2*)((float*)Cout + (size_t)rowa * N + col)
                    = make_float2(acc[mt][nt][0] + b0, acc[mt][nt][1] + b1);
                *(float2*)((float*)Cout + (size_t)(rowa + 8) * N + col)
                    = make_float2(acc[mt][nt][2] + b0, acc[mt][nt][3] + b1);
            }
        }
    }
}

// ---------------------------------------------------------------------------
// Small weight GEMM, k-split: part[kc][i][j] = sum_{c in chunk kc} R(i,c)*L(j,c)
// TRANSR=false: R row-major [i][c].  TRANSR=true: R accessed as R[c][i].
// grid (8, 8, 8): 64x64 tile per block, 64 k-values per chunk.
// ---------------------------------------------------------------------------
template<bool TRANSR>
__global__ void __launch_bounds__(256)
smallgemm_split_kernel(const float* __restrict__ R, const float* __restrict__ L,
                       float* __restrict__ part)
{
    __shared__ float Rs[32][64];
    __shared__ float Ls[32][64];
    const int tid = threadIdx.x;
    const int i0 = blockIdx.x * 64, j0 = blockIdx.y * 64;
    const int kc = blockIdx.z;
    const int tx = tid & 15, ty = tid >> 4;

    float acc[4][4];
#pragma unroll
    for (int a = 0; a < 4; a++)
#pragma unroll
        for (int b = 0; b < 4; b++) acc[a][b] = 0.0f;

    for (int c0 = kc * 64; c0 < kc * 64 + 64; c0 += 32) {
        if (!TRANSR) {
            int i = tid >> 2, cb = (tid & 3) * 8;
            float4 a = *(const float4*)(R + (size_t)(i0 + i) * CC + c0 + cb);
            float4 b = *(const float4*)(R + (size_t)(i0 + i) * CC + c0 + cb + 4);
            Rs[cb+0][i] = a.x; Rs[cb+1][i] = a.y; Rs[cb+2][i] = a.z; Rs[cb+3][i] = a.w;
            Rs[cb+4][i] = b.x; Rs[cb+5][i] = b.y; Rs[cb+6][i] = b.z; Rs[cb+7][i] = b.w;
        } else {
            int c = tid >> 3, ib = (tid & 7) * 8;
            float4 a = *(const float4*)(R + (size_t)(c0 + c) * CC + i0 + ib);
            float4 b = *(const float4*)(R + (size_t)(c0 + c) * CC + i0 + ib + 4);
            Rs[c][ib+0] = a.x; Rs[c][ib+1] = a.y; Rs[c][ib+2] = a.z; Rs[c][ib+3] = a.w;
            Rs[c][ib+4] = b.x; Rs[c][ib+5] = b.y; Rs[c][ib+6] = b.z; Rs[c][ib+7] = b.w;
        }
        {
            int j = tid >> 2, cb = (tid & 3) * 8;
            float4 a = *(const float4*)(L + (size_t)(j0 + j) * CC + c0 + cb);
            float4 b = *(const float4*)(L + (size_t)(j0 + j) * CC + c0 + cb + 4);
            Ls[cb+0][j] = a.x; Ls[cb+1][j] = a.y; Ls[cb+2][j] = a.z; Ls[cb+3][j] = a.w;
            Ls[cb+4][j] = b.x; Ls[cb+5][j] = b.y; Ls[cb+6][j] = b.z; Ls[cb+7][j] = b.w;
        }
        __syncthreads();
#pragma unroll
        for (int c = 0; c < 32; c++) {
            float ri[4], lj[4];
#pragma unroll
            for (int a = 0; a < 4; a++) ri[a] = Rs[c][ty * 4 + a];
#pragma unroll
            for (int b = 0; b < 4; b++) lj[b] = Ls[c][tx * 4 + b];
#pragma unroll
            for (int a = 0; a < 4; a++)
#pragma unroll
                for (int b = 0; b < 4; b++)
                    acc[a][b] = fmaf(ri[a], lj[b], acc[a][b]);
        }
        __syncthreads();
    }

    float* pb = part + (size_t)kc * CC * CC;
#pragma unroll
    for (int a = 0; a < 4; a++)
#pragma unroll
        for (int b = 0; b < 4; b++)
            pb[(size_t)(i0 + ty * 4 + a) * CC + j0 + tx * 4 + b] = acc[a][b];
}

// Combine 8 k-split partials -> bf16 hi (+lo). 4 elems/thread.
template<bool WRITE_LO>
__global__ void __launch_bounds__(256)
wcombine_kernel(const float* __restrict__ part,
                __nv_bfloat16* __restrict__ Ch, __nv_bfloat16* __restrict__ Cl)
{
    size_t i = ((size_t)blockIdx.x * 256 + threadIdx.x) * 4;
    float4 s = make_float4(0.f, 0.f, 0.f, 0.f);
#pragma unroll
    for (int p = 0; p < 8; p++) {
        float4 v = *(const float4*)(part + (size_t)p * CC * CC + i);
        s.x += v.x; s.y += v.y; s.z += v.z; s.w += v.w;
    }
    __nv_bfloat16 h0 = __float2bfloat16(s.x), h1 = __float2bfloat16(s.y);
    __nv_bfloat16 h2 = __float2bfloat16(s.z), h3 = __float2bfloat16(s.w);
    __nv_bfloat162 hp[2] = {{h0, h1}, {h2, h3}};
    *(uint2*)(Ch + i) = *(uint2*)hp;
    if (WRITE_LO) {
        __nv_bfloat162 lp[2] = {
            {__float2bfloat16(s.x - __bfloat162float(h0)),
             __float2bfloat16(s.y - __bfloat162float(h1))},
            {__float2bfloat16(s.z - __bfloat162float(h2)),
             __float2bfloat16(s.w - __bfloat162float(h3))}};
        *(uint2*)(Cl + i) = *(uint2*)lp;
    }
}

// ---------------------------------------------------------------------------
// wkbq[r] = Wk[r,:] . bq   (warp per row, coalesced, bq in smem)
// ---------------------------------------------------------------------------
__global__ void __launch_bounds__(256)
wkbq_kernel(const float* __restrict__ Wk, const float* __restrict__ bq,
            float* __restrict__ wkbq)
{
    __shared__ float b[CC];
    for (int i = threadIdx.x; i < CC; i += 256) b[i] = bq[i];
    __syncthreads();
    const int warp = threadIdx.x >> 5, lane = threadIdx.x & 31;
    const int r = blockIdx.x * 8 + warp;
    const float* Wr = Wk + (size_t)r * CC;
    float acc = 0.0f;
#pragma unroll
    for (int c = lane * 4; c < CC; c += 128) {
        float4 v = *(const float4*)(Wr + c);
        acc += v.x * b[c] + v.y * b[c+1] + v.z * b[c+2] + v.w * b[c+3];
    }
#pragma unroll
    for (int o = 16; o > 0; o >>= 1) acc += __shfl_xor_sync(0xffffffffu, acc, o);
    if (lane == 0) wkbq[r] = acc;
}

// bv2[t] = sum_c bv[c] * Wo[c, t]  (coalesced in t)
__global__ void __launch_bounds__(512)
bv2_kernel(const float* __restrict__ Wo, const float* __restrict__ bv,
           float* __restrict__ bv2)
{
    __shared__ float b[CC];
    for (int i = threadIdx.x; i < CC; i += 512) b[i] = bv[i];
    __syncthreads();
    const int t = threadIdx.x;
    float acc = 0.0f;
    for (int c = 0; c < CC; c++) acc += b[c] * Wo[(size_t)c * CC + t];
    bv2[t] = acc;
}

// bcol[r] = x_r . wkbq  (warp per row)
__global__ void __launch_bounds__(256)
bcol_kernel(const float* __restrict__ x, const float* __restrict__ wkbq,
            float* __restrict__ bcol)
{
    __shared__ float w[CC];
    for (int i = threadIdx.x; i < CC; i += 256) w[i] = wkbq[i];
    __syncthreads();
    const int warp = threadIdx.x >> 5, lane = threadIdx.x & 31;
    const int r = blockIdx.x * 8 + warp;
    const float* xr = x + (size_t)r * CC;
    float acc = 0.0f;
#pragma unroll
    for (int c = lane * 4; c < CC; c += 128) {
        float4 v = *(const float4*)(xr + c);
        acc += v.x * w[c] + v.y * w[c+1] + v.z * w[c+2] + v.w * w[c+3];
    }
#pragma unroll
    for (int o = 16; o > 0; o >>= 1) acc += __shfl_xor_sync(0xffffffffu, acc, o);
    if (lane == 0) bcol[r] = acc;
}

// split fp32 -> bf16 hi/lo
__global__ void __launch_bounds__(256)
split_kernel(const float* __restrict__ x,
             __nv_bfloat16* __restrict__ xh, __nv_bfloat16* __restrict__ xl)
{
    size_t i = ((size_t)blockIdx.x * 256 + threadIdx.x) * 4;
    float4 v = *(const float4*)(x + i);
    __nv_bfloat16 h0 = __float2bfloat16(v.x), h1 = __float2bfloat16(v.y);
    __nv_bfloat16 h2 = __float2bfloat16(v.z), h3 = __float2bfloat16(v.w);
    __nv_bfloat16 l0 = __float2bfloat16(v.x - __bfloat162float(h0));
    __nv_bfloat16 l1 = __float2bfloat16(v.y - __bfloat162float(h1));
    __nv_bfloat16 l2 = __float2bfloat16(v.z - __bfloat162float(h2));
    __nv_bfloat16 l3 = __float2bfloat16(v.w - __bfloat162float(h3));
    __nv_bfloat162 hp[2] = {{h0, h1}, {h2, h3}};
    __nv_bfloat162 lp[2] = {{l0, l1}, {l2, l3}};
    *(uint2*)(xh + i) = *(uint2*)hp;
    *(uint2*)(xl + i) = *(uint2*)lp;
}

// ---------------------------------------------------------------------------
// Column sums of normalized attention (bf16 S), 32-way m-split, 4 cols/thread.
// Fused combine: each block derives rowm/rowinvl for its 128 rows from pm/pl.
// ---------------------------------------------------------------------------
__global__ void __launch_bounds__(256)
colsum_part_kernel(const __nv_bfloat16* __restrict__ S,
                   const float* __restrict__ pm,
                   const float* __restrict__ pl,
                   float* __restrict__ cpart)
{
    __shared__ float sm[128], si[128];
    const int b     = blockIdx.z;
    const int n     = blockIdx.x * 1024 + threadIdx.x * 4;
    const int m0    = blockIdx.y * 128;
    const int rbase = b * 4096;
    if (threadIdx.x < 128) {
        const int r = rbase + m0 + threadIdx.x;
        float M = -3.0e38f;
#pragma unroll
        for (int t = 0; t < 32; t++) M = fmaxf(M, pm[(size_t)t * MM + r]);
        float L = 0.0f;
#pragma unroll
        for (int t = 0; t < 32; t++)
            L += pl[(size_t)t * MM + r] * fexp(pm[(size_t)t * MM + r] - M);
        sm[threadIdx.x] = M;
        si[threadIdx.x] = 1.0f / L;
    }
    __syncthreads();
    const __nv_bfloat16* Sb = S + (size_t)b * SBATCH + (size_t)m0 * 4096 + n;
    float a0 = 0.0f, a1 = 0.0f, a2 = 0.0f, a3 = 0.0f;
#pragma unroll 4
    for (int mm = 0; mm < 128; mm++) {
        uint2 u = *(const uint2*)(Sb + (size_t)mm * 4096);
        float2 f0 = __bfloat1622float2(reinterpret_cast<__nv_bfloat162&>(u.x));
        float2 f1 = __bfloat1622float2(reinterpret_cast<__nv_bfloat162&>(u.y));
        float m = sm[mm], iv = si[mm];
        a0 += fexp(f0.x - m) * iv;
        a1 += fexp(f0.y - m) * iv;
        a2 += fexp(f1.x - m) * iv;
        a3 += fexp(f1.y - m) * iv;
    }
    *(float4*)(cpart + (size_t)blockIdx.y * MM + rbase + n)
        = make_float4(a0, a1, a2, a3);
}

__global__ void __launch_bounds__(256)
colsum_final_kernel(const float* __restrict__ cpart, float* __restrict__ srow)
{
    const int i = blockIdx.x * 256 + threadIdx.x;
    float c = 0.0f;
#pragma unroll
    for (int p = 0; p < 32; p++) c += cpart[(size_t)p * MM + i];
    srow[i] = c / (c + 1e-9f);
}

// ---------------------------------------------------------------------------
// Final elementwise epilogue: out = relu(BN(s[r]*P + bo)) + x
// ---------------------------------------------------------------------------
__global__ void __launch_bounds__(256)
final_epi_kernel(const float* __restrict__ P, const float* __restrict__ srow,
                 const float* __restrict__ x, const float* __restrict__ bo,
                 const float* __restrict__ bns, const float* __restrict__ bnb,
                 const float* __restrict__ bnm, const float* __restrict__ bnv,
                 float* __restrict__ out)
{
    size_t i = ((size_t)blockIdx.x * 256 + threadIdx.x) * 4;
    const int r = (int)(i >> 9);
    const int c = (int)(i & 511);
    const float s = srow[r];
    float4 p = *(const float4*)(P + i);
    float4 xr = *(const float4*)(x + i);
    float pv[4] = {p.x, p.y, p.z, p.w};
    float xv[4] = {xr.x, xr.y, xr.z, xr.w};
    float o[4];
#pragma unroll
    for (int j = 0; j < 4; j++) {
        const int cc = c + j;
        float g = rsqrtf(bnv[cc] + 1e-5f) * bns[cc];
        float v = s * pv[j] + bo[cc];
        v = (v - bnm[cc]) * g + bnb[cc];
        o[j] = fmaxf(v, 0.0f) + xv[j];
    }
    *(float4*)(out + i) = make_float4(o[0], o[1], o[2], o[3]);
}

// ---------------------------------------------------------------------------
extern "C" void kernel_launch(void* const* d_in, const int* in_sizes, int n_in,
                              void* d_out, int out_size)
{
    // metadata order: inputs, Wq, Wk, Wv, Wo, bq, bk, bv, bo, bn_* (two loops!)
    const float* x   = (const float*)d_in[0];
    const float* Wq  = (const float*)d_in[1];
    const float* Wk  = (const float*)d_in[2];
    const float* Wv  = (const float*)d_in[3];
    const float* Wo  = (const float*)d_in[4];
    const float* bq  = (const float*)d_in[5];
    // bk (d_in[6]) only contributes row-constant logit terms -> cancels in softmax.
    const float* bv  = (const float*)d_in[7];
    const float* bo  = (const float*)d_in[8];
    const float* bns = (const float*)d_in[9];
    const float* bnb = (const float*)d_in[10];
    const float* bnm = (const float*)d_in[11];
    const float* bnv = (const float*)d_in[12];
    float* out = (float*)d_out;

    void *xh, *xl, *qh, *P, *S, *qkT, *w2h, *w2l, *part1, *part2;
    void *wkbq, *bv2, *bcol, *zero, *pm, *pl, *cpart, *srow;
    cudaGetSymbolAddress(&xh,   g_xh);   cudaGetSymbolAddress(&xl,   g_xl);
    cudaGetSymbolAddress(&qh,   g_qh);   cudaGetSymbolAddress(&P,    g_P);
    cudaGetSymbolAddress(&S,    g_S);
    cudaGetSymbolAddress(&qkT,  g_qkT);
    cudaGetSymbolAddress(&w2h,  g_w2h);  cudaGetSymbolAddress(&w2l,  g_w2l);
    cudaGetSymbolAddress(&part1, g_part1);
    cudaGetSymbolAddress(&part2, g_part2);
    cudaGetSymbolAddress(&wkbq, g_wkbq); cudaGetSymbolAddress(&bv2,  g_bv2);
    cudaGetSymbolAddress(&bcol, g_bcol); cudaGetSymbolAddress(&zero, g_zero);
    cudaGetSymbolAddress(&pm,    g_pm);
    cudaGetSymbolAddress(&pl,    g_pl);
    cudaGetSymbolAddress(&cpart, g_cpart);
    cudaGetSymbolAddress(&srow,  g_srow);

    static cudaStream_t s2 = nullptr;
    static cudaEvent_t  eFork = nullptr, eQk = nullptr, eP = nullptr, eSplit = nullptr;
    if (s2 == nullptr) {
        cudaStreamCreateWithFlags(&s2, cudaStreamNonBlocking);
        cudaEventCreateWithFlags(&eFork, cudaEventDisableTiming);
        cudaEventCreateWithFlags(&eQk, cudaEventDisableTiming);
        cudaEventCreateWithFlags(&eP, cudaEventDisableTiming);
        cudaEventCreateWithFlags(&eSplit, cudaEventDisableTiming);
        cudaFuncSetAttribute(mma_gemm_kernel<1, 0>,
            cudaFuncAttributeMaxDynamicSharedMemorySize, 49152);
        cudaFuncSetAttribute(mma_gemm_kernel<3, 1>,
            cudaFuncAttributeMaxDynamicSharedMemorySize, 98304);
    }

    dim3 blk(256);
    dim3 gProj(CC / 128, MM / 128);           // (4, 64)

    // Fork s2 at t=0: everything on s2 up to the P-GEMM depends only on
    // harness inputs, not on any kernel.
    cudaEventRecord(eFork, 0);
    cudaStreamWaitEvent(s2, eFork, 0);

    // main: split x into bf16 hi/lo (concurrent with s2 prep)
    split_kernel<<<(MM * CC) / 1024, blk>>>(x, (__nv_bfloat16*)xh, (__nv_bfloat16*)xl);
    cudaEventRecord(eSplit, 0);

    // s2: prep chain (coalesced + k-split for throughput)
    wkbq_kernel<<<CC / 8, blk, 0, s2>>>(Wk, bq, (float*)wkbq);
    bcol_kernel<<<MM / 8, blk, 0, s2>>>(x, (const float*)wkbq, (float*)bcol);
    // Wqk^T[b][a] = sum_c Wk[b,c] * Wq[a,c]
    smallgemm_split_kernel<false><<<dim3(8, 8, 8), blk, 0, s2>>>(
        Wk, Wq, (float*)part1);
    wcombine_kernel<false><<<(CC * CC) / 1024, blk, 0, s2>>>(
        (const float*)part1, (__nv_bfloat16*)qkT, nullptr);
    cudaEventRecord(eQk, s2);
    // W2^T[j2][a] = sum_c Wo[c,j2] * Wv[a,c]
    bv2_kernel<<<1, 512, 0, s2>>>(Wo, bv, (float*)bv2);
    smallgemm_split_kernel<true><<<dim3(8, 8, 8), blk, 0, s2>>>(
        Wo, Wv, (float*)part2);
    wcombine_kernel<true><<<(CC * CC) / 1024, blk, 0, s2>>>(
        (const float*)part2, (__nv_bfloat16*)w2h, (__nv_bfloat16*)w2l);
    cudaStreamWaitEvent(s2, eSplit, 0);
    // P = x @ W2 + bv2 (split-bf16, fp32 out) — overlaps K2 on main
    mma_gemm_kernel<3, 1><<<gProj, blk, 98304, s2>>>(
        (const __nv_bfloat16*)xh, (const __nv_bfloat16*)xl,
        (const __nv_bfloat16*)w2h, (const __nv_bfloat16*)w2l,
        P, CC, CC, (const float*)bv2);
    cudaEventRecord(eP, s2);

    // main: q' = x @ Wqk (needs qkT + bcol from s2, both done by eQk)
    cudaStreamWaitEvent(0, eQk, 0);
    mma_gemm_kernel<1, 0><<<gProj, blk, 49152>>>(
        (const __nv_bfloat16*)xh, nullptr, (const __nv_bfloat16*)qkT, nullptr,
        qh, CC, CC, (const float*)zero);

    // K2: S = q' @ x^T + bcol, fused per-tile softmax stats
    qk_mma_kernel<<<dim3(32, 32, 2), blk>>>(
        (const __nv_bfloat16*)qh, (const __nv_bfloat16*)xh, (__nv_bfloat16*)S,
        (float*)pm, (float*)pl, (const float*)bcol);

    // colsum -> s[n]
    colsum_part_kernel<<<dim3(4, 32, 2), blk>>>((const __nv_bfloat16*)S,
        (const float*)pm, (const float*)pl, (float*)cpart);
    colsum_final_kernel<<<MM / 256, blk>>>((const float*)cpart, (float*)srow);

    // final: out = relu(BN(s[r]*P + bo)) + x   (needs P from s2)
    cudaStreamWaitEvent(0, eP, 0);
    final_epi_kernel<<<(MM * CC) / 1024, blk>>>(
        (const float*)P, (const float*)srow, x, bo, bns, bnb, bnm, bnv, out);
}

// round 14
// speedup vs baseline: 1.5763x; 1.0088x over previous
#include <cuda_runtime.h>
#include <cuda_bf16.h>
#include <math.h>
#include <stdint.h>

// Problem dims (fixed by the dataset)
static constexpr int  BB  = 2;
static constexpr int  NN_ = 4096;
static constexpr int  CC  = 512;
static constexpr int  MM  = BB * NN_;               // 8192 rows total
static constexpr size_t SBATCH = (size_t)NN_ * NN_; // 16777216
static constexpr int  KSP = 16;                     // weight-GEMM k-split

// Scratch (device globals: no cudaMalloc allowed; zero-initialized)
__device__ __align__(256) unsigned short g_xh[(size_t)MM * CC];  // bf16 x hi
__device__ __align__(256) unsigned short g_xl[(size_t)MM * CC];  // bf16 x lo
__device__ __align__(256) unsigned short g_qh[(size_t)MM * CC];  // bf16 q' = x@Wqk
__device__ __align__(256) float          g_P [(size_t)MM * CC];  // fp32 P = x@W2 + bv2
__device__ __align__(256) unsigned short g_S [(size_t)BB * SBATCH]; // bf16 logits
__device__ __align__(256) unsigned short g_qkT[CC * CC];  // bf16 Wqk^T  [b][a]
__device__ __align__(256) unsigned short g_w2h[CC * CC];  // bf16 W2^T hi [j2][a]
__device__ __align__(256) unsigned short g_w2l[CC * CC];  // bf16 W2^T lo
__device__ __align__(256) float g_part1[KSP * CC * CC];   // k-split partials (qkT)
__device__ __align__(256) float g_part2[KSP * CC * CC];   // k-split partials (w2)
__device__ float g_wkbq[CC];     // Wk @ bq
__device__ float g_bv2[CC];      // bv @ Wo
__device__ float g_bcol[MM];     // x @ (Wk@bq)  (column logit bias)
__device__ float g_zero[CC];     // zeros (device globals zero-init)
__device__ float g_pm[32 * MM];
__device__ float g_pl[32 * MM];
__device__ float g_cpart[32 * MM];
__device__ float g_srow[MM];

// ---------------------------------------------------------------------------
// PTX helpers (plain sm_103-compatible: mma.sync / ldmatrix / cp.async)
// ---------------------------------------------------------------------------
__device__ __forceinline__ uint32_t smem_u32(const void* p) {
    uint32_t a;
    asm("{ .reg .u64 t; cvta.to.shared.u64 t, %1; cvt.u32.u64 %0, t; }"
        : "=r"(a) : "l"(p));
    return a;
}
__device__ __forceinline__ void cp_async16(uint32_t dst, const void* src) {
    asm volatile("cp.async.cg.shared.global [%0], [%1], 16;"
                 :: "r"(dst), "l"(src) : "memory");
}
__device__ __forceinline__ void cp_commit() {
    asm volatile("cp.async.commit_group;" ::: "memory");
}
template<int N>
__device__ __forceinline__ void cp_wait() {
    asm volatile("cp.async.wait_group %0;" :: "n"(N) : "memory");
}
__device__ __forceinline__ void ldmatrix_x4(uint32_t& r0, uint32_t& r1,
                                            uint32_t& r2, uint32_t& r3,
                                            uint32_t addr) {
    asm volatile("ldmatrix.sync.aligned.m8n8.x4.shared.b16 {%0,%1,%2,%3}, [%4];"
                 : "=r"(r0), "=r"(r1), "=r"(r2), "=r"(r3) : "r"(addr));
}
__device__ __forceinline__ void mma_bf16(float& c0, float& c1, float& c2, float& c3,
                                         uint32_t a0, uint32_t a1, uint32_t a2, uint32_t a3,
                                         uint32_t b0, uint32_t b1) {
    asm volatile(
        "mma.sync.aligned.m16n8k16.row.col.f32.bf16.bf16.f32 "
        "{%0,%1,%2,%3}, {%4,%5,%6,%7}, {%8,%9}, {%0,%1,%2,%3};"
        : "+f"(c0), "+f"(c1), "+f"(c2), "+f"(c3)
        : "r"(a0), "r"(a1), "r"(a2), "r"(a3), "r"(b0), "r"(b1));
}

// smem tile layout: row-major [row][32 bf16] = 64B/row; 16B granules XOR-swizzled
__device__ __forceinline__ uint32_t sw_off(int row, int kg) {
    return (uint32_t)(row * 64 + ((kg ^ ((row >> 1) & 3)) << 4));
}

// exp via MUFU ex2.approx (1 FMA + 1 MUFU).
__device__ __forceinline__ float fexp(float x) {
    float y = x * 1.4426950408889634f;
    float r;
    asm("ex2.approx.f32 %0, %1;" : "=f"(r) : "f"(y));
    return r;
}

// ---------------------------------------------------------------------------
// K2: S[b] = q'[b] @ x[b]^T + bcol[n]. mma.sync bf16, tile 128x128, BK=32,
// 3-stage cp.async pipeline. Fused epilogue: smem-staged coalesced bf16 S
// store + per-tile softmax partials.
// ---------------------------------------------------------------------------
__global__ void __launch_bounds__(256, 2)
qk_mma_kernel(const __nv_bfloat16* __restrict__ Q,
              const __nv_bfloat16* __restrict__ Kmat,
              __nv_bfloat16* __restrict__ S,
              float* __restrict__ pm, float* __restrict__ pl,
              const float* __restrict__ bcol)
{
    __shared__ __align__(1024) char smem[3 * 16384];
    const uint32_t sbase = smem_u32(smem);

    const int tid = threadIdx.x;
    const int wid = tid >> 5;
    const int lid = tid & 31;
    const int wm  = wid & 3;
    const int wn  = wid >> 2;
    const int n0  = blockIdx.x * 128;
    const int m0  = blockIdx.y * 128;
    const int bz  = blockIdx.z;

    const __nv_bfloat16* Qb = Q    + ((size_t)bz * NN_ + m0) * CC;
    const __nv_bfloat16* Kb = Kmat + ((size_t)bz * NN_ + n0) * CC;

    const int mgrp = lid >> 3;
    const int lr   = lid & 7;
    uint32_t aoff[2][2], boff[4][2];
#pragma unroll
    for (int mt = 0; mt < 2; mt++)
#pragma unroll
        for (int kh = 0; kh < 2; kh++) {
            int row = wm * 32 + mt * 16 + lr + ((mgrp & 1) << 3);
            int kg  = 2 * kh + (mgrp >> 1);
            aoff[mt][kh] = sw_off(row, kg);
        }
#pragma unroll
    for (int i = 0; i < 4; i++)
#pragma unroll
        for (int kh = 0; kh < 2; kh++) {
            int row = wn * 64 + i * 16 + lr + ((mgrp >> 1) << 3);
            int kg  = 2 * kh + (mgrp & 1);
            boff[i][kh] = 8192u + sw_off(row, kg);
        }

    float acc[2][8][4];
#pragma unroll
    for (int mt = 0; mt < 2; mt++)
#pragma unroll
        for (int nt = 0; nt < 8; nt++)
#pragma unroll
            for (int e = 0; e < 4; e++) acc[mt][nt][e] = 0.0f;

    auto load_stage = [&](int kb, int buf) {
        uint32_t dstb = sbase + buf * 16384;
#pragma unroll
        for (int it = 0; it < 2; it++) {
            int idx = tid + it * 256;
            int row = idx >> 2, kg = idx & 3;
            cp_async16(dstb + sw_off(row, kg), Qb + (size_t)row * CC + kb * 32 + kg * 8);
        }
#pragma unroll
        for (int it = 0; it < 2; it++) {
            int idx = tid + it * 256;
            int row = idx >> 2, kg = idx & 3;
            cp_async16(dstb + 8192 + sw_off(row, kg), Kb + (size_t)row * CC + kb * 32 + kg * 8);
        }
        cp_commit();
    };

    load_stage(0, 0);
    load_stage(1, 1);

    const int KB = CC / 32;
    for (int kb = 0; kb < KB; kb++) {
        const int buf = kb % 3;
        if (kb < KB - 1) cp_wait<1>(); else cp_wait<0>();
        __syncthreads();
        if (kb + 2 < KB) load_stage(kb + 2, (kb + 2) % 3);

        const uint32_t stb = sbase + buf * 16384;
#pragma unroll
        for (int kh = 0; kh < 2; kh++) {
            uint32_t af[2][4], bf[4][4];
#pragma unroll
            for (int mt = 0; mt < 2; mt++)
                ldmatrix_x4(af[mt][0], af[mt][1], af[mt][2], af[mt][3],
                            stb + aoff[mt][kh]);
#pragma unroll
            for (int i = 0; i < 4; i++)
                ldmatrix_x4(bf[i][0], bf[i][1], bf[i][2], bf[i][3],
                            stb + boff[i][kh]);
#pragma unroll
            for (int mt = 0; mt < 2; mt++)
#pragma unroll
                for (int i = 0; i < 4; i++) {
                    mma_bf16(acc[mt][2*i][0], acc[mt][2*i][1], acc[mt][2*i][2], acc[mt][2*i][3],
                             af[mt][0], af[mt][1], af[mt][2], af[mt][3],
                             bf[i][0], bf[i][1]);
                    mma_bf16(acc[mt][2*i+1][0], acc[mt][2*i+1][1], acc[mt][2*i+1][2], acc[mt][2*i+1][3],
                             af[mt][0], af[mt][1], af[mt][2], af[mt][3],
                             bf[i][2], bf[i][3]);
                }
        }
    }

    __syncthreads();   // pipeline smem now reusable

    __nv_bfloat16* sS = (__nv_bfloat16*)smem;
    float* s_red = (float*)(smem + 32768);
    float* s_tm  = s_red + 256;
    float* s_l   = s_tm + 128;
    float* s_bc  = s_l + 256;

    if (tid < 128) s_bc[tid] = bcol[(size_t)bz * NN_ + n0 + tid];
    __syncthreads();

    const int grow = lid >> 2;
    const int gcol = (lid & 3) * 2;

    // Add column logit bias into acc (exact bias handling for bq)
#pragma unroll
    for (int mt = 0; mt < 2; mt++)
#pragma unroll
        for (int nt = 0; nt < 8; nt++) {
            const int cl = wn * 64 + nt * 8 + gcol;
            float b0 = s_bc[cl], b1 = s_bc[cl + 1];
            acc[mt][nt][0] += b0; acc[mt][nt][1] += b1;
            acc[mt][nt][2] += b0; acc[mt][nt][3] += b1;
        }

    // Sweep 1: per-thread row maxes over raw fp32 acc
    float pmax[2][2];
#pragma unroll
    for (int mt = 0; mt < 2; mt++) { pmax[mt][0] = -3.0e38f; pmax[mt][1] = -3.0e38f; }
#pragma unroll
    for (int mt = 0; mt < 2; mt++)
#pragma unroll
        for (int nt = 0; nt < 8; nt++) {
            pmax[mt][0] = fmaxf(pmax[mt][0], fmaxf(acc[mt][nt][0], acc[mt][nt][1]));
            pmax[mt][1] = fmaxf(pmax[mt][1], fmaxf(acc[mt][nt][2], acc[mt][nt][3]));
        }
#pragma unroll
    for (int mt = 0; mt < 2; mt++)
#pragma unroll
        for (int h = 0; h < 2; h++) {
            float v = pmax[mt][h];
            v = fmaxf(v, __shfl_xor_sync(0xffffffffu, v, 1));
            v = fmaxf(v, __shfl_xor_sync(0xffffffffu, v, 2));
            if ((lid & 3) == 0)
                s_red[(wm * 32 + mt * 16 + h * 8 + grow) * 2 + wn] = v;
        }
    __syncthreads();
    if (tid < 128) s_tm[tid] = fmaxf(s_red[tid * 2], s_red[tid * 2 + 1]);
    __syncthreads();

    // Sweep 2: stage bf16 S tile in smem + per-thread sumexp
    float psum[2][2] = {{0.0f, 0.0f}, {0.0f, 0.0f}};
#pragma unroll
    for (int mt = 0; mt < 2; mt++) {
        const int rl0 = wm * 32 + mt * 16 + grow;
        const float tm0 = s_tm[rl0];
        const float tm1 = s_tm[rl0 + 8];
#pragma unroll
        for (int nt = 0; nt < 8; nt++) {
            const int cl = wn * 64 + nt * 8 + gcol;
            __nv_bfloat162 h0 = __float22bfloat162_rn(
                make_float2(acc[mt][nt][0], acc[mt][nt][1]));
            __nv_bfloat162 h1 = __float22bfloat162_rn(
                make_float2(acc[mt][nt][2], acc[mt][nt][3]));
            *(__nv_bfloat162*)(sS + rl0 * 128 + cl) = h0;
            *(__nv_bfloat162*)(sS + (rl0 + 8) * 128 + cl) = h1;
            float2 f0 = __bfloat1622float2(h0);
            float2 f1 = __bfloat1622float2(h1);
            psum[mt][0] += fexp(f0.x - tm0) + fexp(f0.y - tm0);
            psum[mt][1] += fexp(f1.x - tm1) + fexp(f1.y - tm1);
        }
    }
#pragma unroll
    for (int mt = 0; mt < 2; mt++)
#pragma unroll
        for (int h = 0; h < 2; h++) {
            float v = psum[mt][h];
            v += __shfl_xor_sync(0xffffffffu, v, 1);
            v += __shfl_xor_sync(0xffffffffu, v, 2);
            if ((lid & 3) == 0)
                s_l[(wm * 32 + mt * 16 + h * 8 + grow) * 2 + wn] = v;
        }
    __syncthreads();

    // Coalesced S store
    {
        __nv_bfloat16* Sg = S + (size_t)bz * SBATCH + (size_t)m0 * NN_ + n0;
#pragma unroll
        for (int it = 0; it < 8; it++) {
            int c   = tid + it * 256;
            int row = c >> 4;
            int off = (c & 15) * 8;
            *(uint4*)(Sg + (size_t)row * NN_ + off) = *(uint4*)(sS + row * 128 + off);
        }
    }
    if (tid < 128) {
        const size_t brow = (size_t)bz * NN_ + m0 + tid;
        pm[(size_t)blockIdx.x * MM + brow] = s_tm[tid];
        pl[(size_t)blockIdx.x * MM + brow] = s_l[tid * 2] + s_l[tid * 2 + 1];
    }
}

// ---------------------------------------------------------------------------
// Generic mma GEMM (TERMS=1 bf16, TERMS=3 split-bf16).
// EPI 0: +bias -> bf16 out (smem-staged coalesced). EPI 1: +bias -> fp32 out.
// ---------------------------------------------------------------------------
template<int TERMS, int EPI>
__global__ void __launch_bounds__(256, 2)
mma_gemm_kernel(const __nv_bfloat16* __restrict__ Ah,
                const __nv_bfloat16* __restrict__ Al,
                const __nv_bfloat16* __restrict__ Bh,
                const __nv_bfloat16* __restrict__ Bl,
                void* __restrict__ Cout, int N, int K,
                const float* __restrict__ bias)
{
    constexpr int STAGE = (TERMS == 3) ? 32768 : 16384;
    constexpr uint32_t BOFF = (TERMS == 3) ? 16384u : 8192u;
    extern __shared__ __align__(1024) char smem[];
    const uint32_t sbase = smem_u32(smem);

    const int tid = threadIdx.x;
    const int wid = tid >> 5;
    const int lid = tid & 31;
    const int wm  = wid & 3;
    const int wn  = wid >> 2;
    const int n0  = blockIdx.x * 128;
    const int m0  = blockIdx.y * 128;

    const __nv_bfloat16* Ahb = Ah + (size_t)m0 * K;
    const __nv_bfloat16* Alb = (TERMS == 3) ? Al + (size_t)m0 * K : nullptr;
    const __nv_bfloat16* Bhb = Bh + (size_t)n0 * K;
    const __nv_bfloat16* Blb = (TERMS == 3) ? Bl + (size_t)n0 * K : nullptr;

    const int mgrp = lid >> 3;
    const int lr   = lid & 7;
    uint32_t aoff[2][2], boff[4][2];
#pragma unroll
    for (int mt = 0; mt < 2; mt++)
#pragma unroll
        for (int kh = 0; kh < 2; kh++) {
            int row = wm * 32 + mt * 16 + lr + ((mgrp & 1) << 3);
            int kg  = 2 * kh + (mgrp >> 1);
            aoff[mt][kh] = sw_off(row, kg);
        }
#pragma unroll
    for (int i = 0; i < 4; i++)
#pragma unroll
        for (int kh = 0; kh < 2; kh++) {
            int row = wn * 64 + i * 16 + lr + ((mgrp >> 1) << 3);
            int kg  = 2 * kh + (mgrp & 1);
            boff[i][kh] = BOFF + sw_off(row, kg);
        }

    float acc[2][8][4];
#pragma unroll
    for (int mt = 0; mt < 2; mt++)
#pragma unroll
        for (int nt = 0; nt < 8; nt++)
#pragma unroll
            for (int e = 0; e < 4; e++) acc[mt][nt][e] = 0.0f;

    auto load_stage = [&](int kb, int buf) {
        uint32_t dstb = sbase + buf * STAGE;
#pragma unroll
        for (int it = 0; it < 2; it++) {
            int idx = tid + it * 256;
            int row = idx >> 2, kg = idx & 3;
            size_t goff = (size_t)row * K + kb * 32 + kg * 8;
            uint32_t so = sw_off(row, kg);
            cp_async16(dstb + so, Ahb + goff);
            if (TERMS == 3) cp_async16(dstb + 8192u + so, Alb + goff);
            cp_async16(dstb + BOFF + so, Bhb + goff);
            if (TERMS == 3) cp_async16(dstb + BOFF + 8192u + so, Blb + goff);
        }
        cp_commit();
    };

    load_stage(0, 0);
    load_stage(1, 1);

    const int KB = K / 32;
    for (int kb = 0; kb < KB; kb++) {
        const int buf = kb % 3;
        if (kb < KB - 1) cp_wait<1>(); else cp_wait<0>();
        __syncthreads();
        if (kb + 2 < KB) load_stage(kb + 2, (kb + 2) % 3);

        const uint32_t stb = sbase + buf * STAGE;
#pragma unroll
        for (int kh = 0; kh < 2; kh++) {
            uint32_t afh[2][4], bfh[4][4];
            uint32_t afl[2][4], bfl[4][4];
#pragma unroll
            for (int mt = 0; mt < 2; mt++) {
                ldmatrix_x4(afh[mt][0], afh[mt][1], afh[mt][2], afh[mt][3],
                            stb + aoff[mt][kh]);
                if (TERMS == 3)
                    ldmatrix_x4(afl[mt][0], afl[mt][1], afl[mt][2], afl[mt][3],
                                stb + 8192u + aoff[mt][kh]);
            }
#pragma unroll
            for (int i = 0; i < 4; i++) {
                ldmatrix_x4(bfh[i][0], bfh[i][1], bfh[i][2], bfh[i][3],
                            stb + boff[i][kh]);
                if (TERMS == 3)
                    ldmatrix_x4(bfl[i][0], bfl[i][1], bfl[i][2], bfl[i][3],
                                stb + 8192u + boff[i][kh]);
            }
#pragma unroll
            for (int mt = 0; mt < 2; mt++)
#pragma unroll
                for (int i = 0; i < 4; i++) {
#pragma unroll
                    for (int h = 0; h < 2; h++) {
                        float* c0 = acc[mt][2*i + h];
                        mma_bf16(c0[0], c0[1], c0[2], c0[3],
                                 afh[mt][0], afh[mt][1], afh[mt][2], afh[mt][3],
                                 bfh[i][2*h], bfh[i][2*h + 1]);
                        if (TERMS == 3) {
                            mma_bf16(c0[0], c0[1], c0[2], c0[3],
                                     afh[mt][0], afh[mt][1], afh[mt][2], afh[mt][3],
                                     bfl[i][2*h], bfl[i][2*h + 1]);
                            mma_bf16(c0[0], c0[1], c0[2], c0[3],
                                     afl[mt][0], afl[mt][1], afl[mt][2], afl[mt][3],
                                     bfh[i][2*h], bfh[i][2*h + 1]);
                        }
                    }
                }
        }
    }

    const int grow = lid >> 2;
    const int gcol = (lid & 3) * 2;
    if (EPI == 0) {
        __syncthreads();
        __nv_bfloat16* sC = (__nv_bfloat16*)smem;
#pragma unroll
        for (int mt = 0; mt < 2; mt++) {
            const int rl0 = wm * 32 + mt * 16 + grow;
#pragma unroll
            for (int nt = 0; nt < 8; nt++) {
                const int cl  = wn * 64 + nt * 8 + gcol;
                const int col = n0 + cl;
                float b0 = bias[col], b1 = bias[col + 1];
                *(__nv_bfloat162*)(sC + rl0 * 128 + cl) = __float22bfloat162_rn(
                    make_float2(acc[mt][nt][0] + b0, acc[mt][nt][1] + b1));
                *(__nv_bfloat162*)(sC + (rl0 + 8) * 128 + cl) = __float22bfloat162_rn(
                    make_float2(acc[mt][nt][2] + b0, acc[mt][nt][3] + b1));
            }
        }
        __syncthreads();
        __nv_bfloat16* Cg = (__nv_bfloat16*)Cout + (size_t)m0 * N + n0;
#pragma unroll
        for (int it = 0; it < 8; it++) {
            int c   = tid + it * 256;
            int row = c >> 4;
            int off = (c & 15) * 8;
            *(uint4*)(Cg + (size_t)row * N + off) = *(uint4*)(sC + row * 128 + off);
        }
    } else {
#pragma unroll
        for (int mt = 0; mt < 2; mt++) {
#pragma unroll
            for (int nt = 0; nt < 8; nt++) {
                const int col  = n0 + wn * 64 + nt * 8 + gcol;
                const int rowa = m0 + wm * 32 + mt * 16 + grow;
                float b0 = bias[col], b1 = bias[col + 1];
                *(float2*)((float*)Cout + (size_t)rowa * N + col)
                    = make_float2(acc[mt][nt][0] + b0, acc[mt][nt][1] + b1);
                *(float2*)((float*)Cout + (size_t)(rowa + 8) * N + col)
                    = make_float2(acc[mt][nt][2] + b0, acc[mt][nt][3] + b1);
            }
        }
    }
}

// ---------------------------------------------------------------------------
// Small weight GEMM, k-split: part[kc][i][j] = sum_{c in chunk kc} R(i,c)*L(j,c)
// TRANSR=false: R row-major [i][c].  TRANSR=true: R accessed as R[c][i].
// grid (8, 8, KSP): 64x64 tile per block, 512/KSP k-values per chunk.
// ---------------------------------------------------------------------------
template<bool TRANSR>
__global__ void __launch_bounds__(256)
smallgemm_split_kernel(const float* __restrict__ R, const float* __restrict__ L,
                       float* __restrict__ part)
{
    __shared__ float Rs[32][64];
    __shared__ float Ls[32][64];
    const int tid = threadIdx.x;
    const int i0 = blockIdx.x * 64, j0 = blockIdx.y * 64;
    const int kc = blockIdx.z;
    const int tx = tid & 15, ty = tid >> 4;
    constexpr int KCH = CC / KSP;   // 32

    float acc[4][4];
#pragma unroll
    for (int a = 0; a < 4; a++)
#pragma unroll
        for (int b = 0; b < 4; b++) acc[a][b] = 0.0f;

    for (int c0 = kc * KCH; c0 < kc * KCH + KCH; c0 += 32) {
        if (!TRANSR) {
            int i = tid >> 2, cb = (tid & 3) * 8;
            float4 a = *(const float4*)(R + (size_t)(i0 + i) * CC + c0 + cb);
            float4 b = *(const float4*)(R + (size_t)(i0 + i) * CC + c0 + cb + 4);
            Rs[cb+0][i] = a.x; Rs[cb+1][i] = a.y; Rs[cb+2][i] = a.z; Rs[cb+3][i] = a.w;
            Rs[cb+4][i] = b.x; Rs[cb+5][i] = b.y; Rs[cb+6][i] = b.z; Rs[cb+7][i] = b.w;
        } else {
            int c = tid >> 3, ib = (tid & 7) * 8;
            float4 a = *(const float4*)(R + (size_t)(c0 + c) * CC + i0 + ib);
            float4 b = *(const float4*)(R + (size_t)(c0 + c) * CC + i0 + ib + 4);
            Rs[c][ib+0] = a.x; Rs[c][ib+1] = a.y; Rs[c][ib+2] = a.z; Rs[c][ib+3] = a.w;
            Rs[c][ib+4] = b.x; Rs[c][ib+5] = b.y; Rs[c][ib+6] = b.z; Rs[c][ib+7] = b.w;
        }
        {
            int j = tid >> 2, cb = (tid & 3) * 8;
            float4 a = *(const float4*)(L + (size_t)(j0 + j) * CC + c0 + cb);
            float4 b = *(const float4*)(L + (size_t)(j0 + j) * CC + c0 + cb + 4);
            Ls[cb+0][j] = a.x; Ls[cb+1][j] = a.y; Ls[cb+2][j] = a.z; Ls[cb+3][j] = a.w;
            Ls[cb+4][j] = b.x; Ls[cb+5][j] = b.y; Ls[cb+6][j] = b.z; Ls[cb+7][j] = b.w;
        }
        __syncthreads();
#pragma unroll
        for (int c = 0; c < 32; c++) {
            float ri[4], lj[4];
#pragma unroll
            for (int a = 0; a < 4; a++) ri[a] = Rs[c][ty * 4 + a];
#pragma unroll
            for (int b = 0; b < 4; b++) lj[b] = Ls[c][tx * 4 + b];
#pragma unroll
            for (int a = 0; a < 4; a++)
#pragma unroll
                for (int b = 0; b < 4; b++)
                    acc[a][b] = fmaf(ri[a], lj[b], acc[a][b]);
        }
        __syncthreads();
    }

    float* pb = part + (size_t)kc * CC * CC;
#pragma unroll
    for (int a = 0; a < 4; a++)
#pragma unroll
        for (int b = 0; b < 4; b++)
            pb[(size_t)(i0 + ty * 4 + a) * CC + j0 + tx * 4 + b] = acc[a][b];
}

// Combine KSP k-split partials -> bf16 hi (+lo). 4 elems/thread.
template<bool WRITE_LO>
__global__ void __launch_bounds__(256)
wcombine_kernel(const float* __restrict__ part,
                __nv_bfloat16* __restrict__ Ch, __nv_bfloat16* __restrict__ Cl)
{
    size_t i = ((size_t)blockIdx.x * 256 + threadIdx.x) * 4;
    float4 s = make_float4(0.f, 0.f, 0.f, 0.f);
#pragma unroll
    for (int p = 0; p < KSP; p++) {
        float4 v = *(const float4*)(part + (size_t)p * CC * CC + i);
        s.x += v.x; s.y += v.y; s.z += v.z; s.w += v.w;
    }
    __nv_bfloat16 h0 = __float2bfloat16(s.x), h1 = __float2bfloat16(s.y);
    __nv_bfloat16 h2 = __float2bfloat16(s.z), h3 = __float2bfloat16(s.w);
    __nv_bfloat162 hp[2] = {{h0, h1}, {h2, h3}};
    *(uint2*)(Ch + i) = *(uint2*)hp;
    if (WRITE_LO) {
        __nv_bfloat162 lp[2] = {
            {__float2bfloat16(s.x - __bfloat162float(h0)),
             __float2bfloat16(s.y - __bfloat162float(h1))},
            {__float2bfloat16(s.z - __bfloat162float(h2)),
             __float2bfloat16(s.w - __bfloat162float(h3))}};
        *(uint2*)(Cl + i) = *(uint2*)lp;
    }
}

// ---------------------------------------------------------------------------
// wkbq[r] = Wk[r,:] . bq   (warp per row, coalesced, bq in smem)
// ---------------------------------------------------------------------------
__global__ void __launch_bounds__(256)
wkbq_kernel(const float* __restrict__ Wk, const float* __restrict__ bq,
            float* __restrict__ wkbq)
{
    __shared__ float b[CC];
    for (int i = threadIdx.x; i < CC; i += 256) b[i] = bq[i];
    __syncthreads();
    const int warp = threadIdx.x >> 5, lane = threadIdx.x & 31;
    const int r = blockIdx.x * 8 + warp;
    const float* Wr = Wk + (size_t)r * CC;
    float acc = 0.0f;
#pragma unroll
    for (int c = lane * 4; c < CC; c += 128) {
        float4 v = *(const float4*)(Wr + c);
        acc += v.x * b[c] + v.y * b[c+1] + v.z * b[c+2] + v.w * b[c+3];
    }
#pragma unroll
    for (int o = 16; o > 0; o >>= 1) acc += __shfl_xor_sync(0xffffffffu, acc, o);
    if (lane == 0) wkbq[r] = acc;
}

// bv2[t] = sum_c bv[c] * Wo[c, t]  (coalesced in t)
__global__ void __launch_bounds__(512)
bv2_kernel(const float* __restrict__ Wo, const float* __restrict__ bv,
           float* __restrict__ bv2)
{
    __shared__ float b[CC];
    for (int i = threadIdx.x; i < CC; i += 512) b[i] = bv[i];
    __syncthreads();
    const int t = threadIdx.x;
    float acc = 0.0f;
    for (int c = 0; c < CC; c++) acc += b[c] * Wo[(size_t)c * CC + t];
    bv2[t] = acc;
}

// bcol[r] = x_r . wkbq  (warp per row)
__global__ void __launch_bounds__(256)
bcol_kernel(const float* __restrict__ x, const float* __restrict__ wkbq,
            float* __restrict__ bcol)
{
    __shared__ float w[CC];
    for (int i = threadIdx.x; i < CC; i += 256) w[i] = wkbq[i];
    __syncthreads();
    const int warp = threadIdx.x >> 5, lane = threadIdx.x & 31;
    const int r = blockIdx.x * 8 + warp;
    const float* xr = x + (size_t)r * CC;
    float acc = 0.0f;
#pragma unroll
    for (int c = lane * 4; c < CC; c += 128) {
        float4 v = *(const float4*)(xr + c);
        acc += v.x * w[c] + v.y * w[c+1] + v.z * w[c+2] + v.w * w[c+3];
    }
#pragma unroll
    for (int o = 16; o > 0; o >>= 1) acc += __shfl_xor_sync(0xffffffffu, acc, o);
    if (lane == 0) bcol[r] = acc;
}

// split fp32 -> bf16 hi/lo
__global__ void __launch_bounds__(256)
split_kernel(const float* __restrict__ x,
             __nv_bfloat16* __restrict__ xh, __nv_bfloat16* __restrict__ xl)
{
    size_t i = ((size_t)blockIdx.x * 256 + threadIdx.x) * 4;
    float4 v = *(const float4*)(x + i);
    __nv_bfloat16 h0 = __float2bfloat16(v.x), h1 = __float2bfloat16(v.y);
    __nv_bfloat16 h2 = __float2bfloat16(v.z), h3 = __float2bfloat16(v.w);
    __nv_bfloat16 l0 = __float2bfloat16(v.x - __bfloat162float(h0));
    __nv_bfloat16 l1 = __float2bfloat16(v.y - __bfloat162float(h1));
    __nv_bfloat16 l2 = __float2bfloat16(v.z - __bfloat162float(h2));
    __nv_bfloat16 l3 = __float2bfloat16(v.w - __bfloat162float(h3));
    __nv_bfloat162 hp[2] = {{h0, h1}, {h2, h3}};
    __nv_bfloat162 lp[2] = {{l0, l1}, {l2, l3}};
    *(uint2*)(xh + i) = *(uint2*)hp;
    *(uint2*)(xl + i) = *(uint2*)lp;
}

// ---------------------------------------------------------------------------
// Column sums of normalized attention (bf16 S), 32-way m-split, 4 cols/thread.
// Fused combine: each block derives rowm/rowinvl for its 128 rows from pm/pl.
// ---------------------------------------------------------------------------
__global__ void __launch_bounds__(256)
colsum_part_kernel(const __nv_bfloat16* __restrict__ S,
                   const float* __restrict__ pm,
                   const float* __restrict__ pl,
                   float* __restrict__ cpart)
{
    __shared__ float sm[128], si[128];
    const int b     = blockIdx.z;
    const int n     = blockIdx.x * 1024 + threadIdx.x * 4;
    const int m0    = blockIdx.y * 128;
    const int rbase = b * 4096;
    if (threadIdx.x < 128) {
        const int r = rbase + m0 + threadIdx.x;
        float M = -3.0e38f;
#pragma unroll
        for (int t = 0; t < 32; t++) M = fmaxf(M, pm[(size_t)t * MM + r]);
        float L = 0.0f;
#pragma unroll
        for (int t = 0; t < 32; t++)
            L += pl[(size_t)t * MM + r] * fexp(pm[(size_t)t * MM + r] - M);
        sm[threadIdx.x] = M;
        si[threadIdx.x] = 1.0f / L;
    }
    __syncthreads();
    const __nv_bfloat16* Sb = S + (size_t)b * SBATCH + (size_t)m0 * 4096 + n;
    float a0 = 0.0f, a1 = 0.0f, a2 = 0.0f, a3 = 0.0f;
#pragma unroll 4
    for (int mm = 0; mm < 128; mm++) {
        uint2 u = *(const uint2*)(Sb + (size_t)mm * 4096);
        float2 f0 = __bfloat1622float2(reinterpret_cast<__nv_bfloat162&>(u.x));
        float2 f1 = __bfloat1622float2(reinterpret_cast<__nv_bfloat162&>(u.y));
        float m = sm[mm], iv = si[mm];
        a0 += fexp(f0.x - m) * iv;
        a1 += fexp(f0.y - m) * iv;
        a2 += fexp(f1.x - m) * iv;
        a3 += fexp(f1.y - m) * iv;
    }
    *(float4*)(cpart + (size_t)blockIdx.y * MM + rbase + n)
        = make_float4(a0, a1, a2, a3);
}

__global__ void __launch_bounds__(256)
colsum_final_kernel(const float* __restrict__ cpart, float* __restrict__ srow)
{
    const int i = blockIdx.x * 256 + threadIdx.x;
    float c = 0.0f;
#pragma unroll
    for (int p = 0; p < 32; p++) c += cpart[(size_t)p * MM + i];
    srow[i] = c / (c + 1e-9f);
}

// ---------------------------------------------------------------------------
// Final elementwise epilogue: out = relu(BN(s[r]*P + bo)) + x
// ---------------------------------------------------------------------------
__global__ void __launch_bounds__(256)
final_epi_kernel(const float* __restrict__ P, const float* __restrict__ srow,
                 const float* __restrict__ x, const float* __restrict__ bo,
                 const float* __restrict__ bns, const float* __restrict__ bnb,
                 const float* __restrict__ bnm, const float* __restrict__ bnv,
                 float* __restrict__ out)
{
    size_t i = ((size_t)blockIdx.x * 256 + threadIdx.x) * 4;
    const int r = (int)(i >> 9);
    const int c = (int)(i & 511);
    const float s = srow[r];
    float4 p = *(const float4*)(P + i);
    float4 xr = *(const float4*)(x + i);
    float pv[4] = {p.x, p.y, p.z, p.w};
    float xv[4] = {xr.x, xr.y, xr.z, xr.w};
    float o[4];
#pragma unroll
    for (int j = 0; j < 4; j++) {
        const int cc = c + j;
        float g = rsqrtf(bnv[cc] + 1e-5f) * bns[cc];
        float v = s * pv[j] + bo[cc];
        v = (v - bnm[cc]) * g + bnb[cc];
        o[j] = fmaxf(v, 0.0f) + xv[j];
    }
    *(float4*)(out + i) = make_float4(o[0], o[1], o[2], o[3]);
}

// ---------------------------------------------------------------------------
extern "C" void kernel_launch(void* const* d_in, const int* in_sizes, int n_in,
                              void* d_out, int out_size)
{
    // metadata order: inputs, Wq, Wk, Wv, Wo, bq, bk, bv, bo, bn_* (two loops!)
    const float* x   = (const float*)d_in[0];
    const float* Wq  = (const float*)d_in[1];
    const float* Wk  = (const float*)d_in[2];
    const float* Wv  = (const float*)d_in[3];
    const float* Wo  = (const float*)d_in[4];
    const float* bq  = (const float*)d_in[5];
    // bk (d_in[6]) only contributes row-constant logit terms -> cancels in softmax.
    const float* bv  = (const float*)d_in[7];
    const float* bo  = (const float*)d_in[8];
    const float* bns = (const float*)d_in[9];
    const float* bnb = (const float*)d_in[10];
    const float* bnm = (const float*)d_in[11];
    const float* bnv = (const float*)d_in[12];
    float* out = (float*)d_out;

    void *xh, *xl, *qh, *P, *S, *qkT, *w2h, *w2l, *part1, *part2;
    void *wkbq, *bv2, *bcol, *zero, *pm, *pl, *cpart, *srow;
    cudaGetSymbolAddress(&xh,   g_xh);   cudaGetSymbolAddress(&xl,   g_xl);
    cudaGetSymbolAddress(&qh,   g_qh);   cudaGetSymbolAddress(&P,    g_P);
    cudaGetSymbolAddress(&S,    g_S);
    cudaGetSymbolAddress(&qkT,  g_qkT);
    cudaGetSymbolAddress(&w2h,  g_w2h);  cudaGetSymbolAddress(&w2l,  g_w2l);
    cudaGetSymbolAddress(&part1, g_part1);
    cudaGetSymbolAddress(&part2, g_part2);
    cudaGetSymbolAddress(&wkbq, g_wkbq); cudaGetSymbolAddress(&bv2,  g_bv2);
    cudaGetSymbolAddress(&bcol, g_bcol); cudaGetSymbolAddress(&zero, g_zero);
    cudaGetSymbolAddress(&pm,    g_pm);
    cudaGetSymbolAddress(&pl,    g_pl);
    cudaGetSymbolAddress(&cpart, g_cpart);
    cudaGetSymbolAddress(&srow,  g_srow);

    static cudaStream_t s2 = nullptr;
    static cudaEvent_t  eFork = nullptr, eQk = nullptr, eBcol = nullptr,
                        eP = nullptr, eSplit = nullptr;
    if (s2 == nullptr) {
        cudaStreamCreateWithFlags(&s2, cudaStreamNonBlocking);
        cudaEventCreateWithFlags(&eFork, cudaEventDisableTiming);
        cudaEventCreateWithFlags(&eQk, cudaEventDisableTiming);
        cudaEventCreateWithFlags(&eBcol, cudaEventDisableTiming);
        cudaEventCreateWithFlags(&eP, cudaEventDisableTiming);
        cudaEventCreateWithFlags(&eSplit, cudaEventDisableTiming);
        cudaFuncSetAttribute(mma_gemm_kernel<1, 0>,
            cudaFuncAttributeMaxDynamicSharedMemorySize, 49152);
        cudaFuncSetAttribute(mma_gemm_kernel<3, 1>,
            cudaFuncAttributeMaxDynamicSharedMemorySize, 98304);
    }

    dim3 blk(256);
    dim3 gProj(CC / 128, MM / 128);           // (4, 64)

    // Fork s2 at t=0: everything on s2 depends only on harness inputs.
    cudaEventRecord(eFork, 0);
    cudaStreamWaitEvent(s2, eFork, 0);

    // main: split x into bf16 hi/lo (concurrent with s2 prep)
    split_kernel<<<(MM * CC) / 1024, blk>>>(x, (__nv_bfloat16*)xh, (__nv_bfloat16*)xl);
    cudaEventRecord(eSplit, 0);

    // s2: qkT chain FIRST (it gates q' on main), bcol deferred after eQk.
    wkbq_kernel<<<CC / 8, blk, 0, s2>>>(Wk, bq, (float*)wkbq);
    smallgemm_split_kernel<false><<<dim3(8, 8, KSP), blk, 0, s2>>>(
        Wk, Wq, (float*)part1);
    wcombine_kernel<false><<<(CC * CC) / 1024, blk, 0, s2>>>(
        (const float*)part1, (__nv_bfloat16*)qkT, nullptr);
    cudaEventRecord(eQk, s2);
    // bcol hides under q' on main.
    bcol_kernel<<<MM / 8, blk, 0, s2>>>(x, (const float*)wkbq, (float*)bcol);
    cudaEventRecord(eBcol, s2);
    // W2 chain + P GEMM (overlaps K2 on main)
    bv2_kernel<<<1, 512, 0, s2>>>(Wo, bv, (float*)bv2);
    smallgemm_split_kernel<true><<<dim3(8, 8, KSP), blk, 0, s2>>>(
        Wo, Wv, (float*)part2);
    wcombine_kernel<true><<<(CC * CC) / 1024, blk, 0, s2>>>(
        (const float*)part2, (__nv_bfloat16*)w2h, (__nv_bfloat16*)w2l);
    cudaStreamWaitEvent(s2, eSplit, 0);
    mma_gemm_kernel<3, 1><<<gProj, blk, 98304, s2>>>(
        (const __nv_bfloat16*)xh, (const __nv_bfloat16*)xl,
        (const __nv_bfloat16*)w2h, (const __nv_bfloat16*)w2l,
        P, CC, CC, (const float*)bv2);
    cudaEventRecord(eP, s2);

    // main: q' = x @ Wqk (needs qkT from s2)
    cudaStreamWaitEvent(0, eQk, 0);
    mma_gemm_kernel<1, 0><<<gProj, blk, 49152>>>(
        (const __nv_bfloat16*)xh, nullptr, (const __nv_bfloat16*)qkT, nullptr,
        qh, CC, CC, (const float*)zero);

    // K2: S = q' @ x^T + bcol, fused per-tile softmax stats
    cudaStreamWaitEvent(0, eBcol, 0);
    qk_mma_kernel<<<dim3(32, 32, 2), blk>>>(
        (const __nv_bfloat16*)qh, (const __nv_bfloat16*)xh, (__nv_bfloat16*)S,
        (float*)pm, (float*)pl, (const float*)bcol);

    // colsum -> s[n]
    colsum_part_kernel<<<dim3(4, 32, 2), blk>>>((const __nv_bfloat16*)S,
        (const float*)pm, (const float*)pl, (float*)cpart);
    colsum_final_kernel<<<MM / 256, blk>>>((const float*)cpart, (float*)srow);

    // final: out = relu(BN(s[r]*P + bo)) + x   (needs P from s2)
    cudaStreamWaitEvent(0, eP, 0);
    final_epi_kernel<<<(MM * CC) / 1024, blk>>>(
        (const float*)P, (const float*)srow, x, bo, bns, bnb, bnm, bnv, out);
}

// round 15
// speedup vs baseline: 1.5768x; 1.0003x over previous
#include <cuda_runtime.h>
#include <cuda_bf16.h>
#include <math.h>
#include <stdint.h>

// Problem dims (fixed by the dataset)
static constexpr int  BB  = 2;
static constexpr int  NN_ = 4096;
static constexpr int  CC  = 512;
static constexpr int  MM  = BB * NN_;               // 8192 rows total
static constexpr size_t SBATCH = (size_t)NN_ * NN_; // 16777216
static constexpr int  KSP = 16;                     // weight-GEMM k-split

// Scratch (device globals: no cudaMalloc allowed; zero-initialized)
__device__ __align__(256) unsigned short g_xh[(size_t)MM * CC];  // bf16 x hi
__device__ __align__(256) unsigned short g_xl[(size_t)MM * CC];  // bf16 x lo
__device__ __align__(256) unsigned short g_qh[(size_t)MM * CC];  // bf16 q' = x@Wqk
__device__ __align__(256) float          g_P [(size_t)MM * CC];  // fp32 P = x@W2 + bv2
__device__ __align__(256) unsigned short g_E [(size_t)BB * SBATCH]; // bf16 exp(S - tile max)
__device__ __align__(256) unsigned short g_qkT[CC * CC];  // bf16 Wqk^T  [b][a]
__device__ __align__(256) unsigned short g_w2h[CC * CC];  // bf16 W2^T hi [j2][a]
__device__ __align__(256) unsigned short g_w2l[CC * CC];  // bf16 W2^T lo
__device__ __align__(256) float g_part1[KSP * CC * CC];   // k-split partials (qkT)
__device__ __align__(256) float g_part2[KSP * CC * CC];   // k-split partials (w2)
__device__ float g_wkbq[CC];     // Wk @ bq
__device__ float g_bv2[CC];      // bv @ Wo
__device__ float g_bcol[MM];     // x @ (Wk@bq)  (column logit bias)
__device__ float g_zero[CC];     // zeros (device globals zero-init)
__device__ float g_pm[32 * MM];  // per-(n-tile,row) tile max of S
__device__ float g_pl[32 * MM];  // per-(n-tile,row) sum of stored bf16 E
__device__ float g_cpart[32 * MM];
__device__ float g_srow[MM];

// ---------------------------------------------------------------------------
// PTX helpers (plain sm_103-compatible: mma.sync / ldmatrix / cp.async)
// ---------------------------------------------------------------------------
__device__ __forceinline__ uint32_t smem_u32(const void* p) {
    uint32_t a;
    asm("{ .reg .u64 t; cvta.to.shared.u64 t, %1; cvt.u32.u64 %0, t; }"
        : "=r"(a) : "l"(p));
    return a;
}
__device__ __forceinline__ void cp_async16(uint32_t dst, const void* src) {
    asm volatile("cp.async.cg.shared.global [%0], [%1], 16;"
                 :: "r"(dst), "l"(src) : "memory");
}
__device__ __forceinline__ void cp_commit() {
    asm volatile("cp.async.commit_group;" ::: "memory");
}
template<int N>
__device__ __forceinline__ void cp_wait() {
    asm volatile("cp.async.wait_group %0;" :: "n"(N) : "memory");
}
__device__ __forceinline__ void ldmatrix_x4(uint32_t& r0, uint32_t& r1,
                                            uint32_t& r2, uint32_t& r3,
                                            uint32_t addr) {
    asm volatile("ldmatrix.sync.aligned.m8n8.x4.shared.b16 {%0,%1,%2,%3}, [%4];"
                 : "=r"(r0), "=r"(r1), "=r"(r2), "=r"(r3) : "r"(addr));
}
__device__ __forceinline__ void mma_bf16(float& c0, float& c1, float& c2, float& c3,
                                         uint32_t a0, uint32_t a1, uint32_t a2, uint32_t a3,
                                         uint32_t b0, uint32_t b1) {
    asm volatile(
        "mma.sync.aligned.m16n8k16.row.col.f32.bf16.bf16.f32 "
        "{%0,%1,%2,%3}, {%4,%5,%6,%7}, {%8,%9}, {%0,%1,%2,%3};"
        : "+f"(c0), "+f"(c1), "+f"(c2), "+f"(c3)
        : "r"(a0), "r"(a1), "r"(a2), "r"(a3), "r"(b0), "r"(b1));
}

// smem tile layout: row-major [row][32 bf16] = 64B/row; 16B granules XOR-swizzled
__device__ __forceinline__ uint32_t sw_off(int row, int kg) {
    return (uint32_t)(row * 64 + ((kg ^ ((row >> 1) & 3)) << 4));
}

// exp via MUFU ex2.approx (1 FMA + 1 MUFU).
__device__ __forceinline__ float fexp(float x) {
    float y = x * 1.4426950408889634f;
    float r;
    asm("ex2.approx.f32 %0, %1;" : "=f"(r) : "f"(y));
    return r;
}

// ---------------------------------------------------------------------------
// K2: S = q' @ x^T + bcol. Fused epilogue now stores E = bf16(exp(S - tm))
// (tm = per-(n-tile,row) max) and pl = sum of the STORED bf16 values, so the
// downstream colsum is a pure weighted sum (no exp).
// ---------------------------------------------------------------------------
__global__ void __launch_bounds__(256, 2)
qk_mma_kernel(const __nv_bfloat16* __restrict__ Q,
              const __nv_bfloat16* __restrict__ Kmat,
              __nv_bfloat16* __restrict__ E,
              float* __restrict__ pm, float* __restrict__ pl,
              const float* __restrict__ bcol)
{
    __shared__ __align__(1024) char smem[3 * 16384];
    const uint32_t sbase = smem_u32(smem);

    const int tid = threadIdx.x;
    const int wid = tid >> 5;
    const int lid = tid & 31;
    const int wm  = wid & 3;
    const int wn  = wid >> 2;
    const int n0  = blockIdx.x * 128;
    const int m0  = blockIdx.y * 128;
    const int bz  = blockIdx.z;

    const __nv_bfloat16* Qb = Q    + ((size_t)bz * NN_ + m0) * CC;
    const __nv_bfloat16* Kb = Kmat + ((size_t)bz * NN_ + n0) * CC;

    const int mgrp = lid >> 3;
    const int lr   = lid & 7;
    uint32_t aoff[2][2], boff[4][2];
#pragma unroll
    for (int mt = 0; mt < 2; mt++)
#pragma unroll
        for (int kh = 0; kh < 2; kh++) {
            int row = wm * 32 + mt * 16 + lr + ((mgrp & 1) << 3);
            int kg  = 2 * kh + (mgrp >> 1);
            aoff[mt][kh] = sw_off(row, kg);
        }
#pragma unroll
    for (int i = 0; i < 4; i++)
#pragma unroll
        for (int kh = 0; kh < 2; kh++) {
            int row = wn * 64 + i * 16 + lr + ((mgrp >> 1) << 3);
            int kg  = 2 * kh + (mgrp & 1);
            boff[i][kh] = 8192u + sw_off(row, kg);
        }

    float acc[2][8][4];
#pragma unroll
    for (int mt = 0; mt < 2; mt++)
#pragma unroll
        for (int nt = 0; nt < 8; nt++)
#pragma unroll
            for (int e = 0; e < 4; e++) acc[mt][nt][e] = 0.0f;

    auto load_stage = [&](int kb, int buf) {
        uint32_t dstb = sbase + buf * 16384;
#pragma unroll
        for (int it = 0; it < 2; it++) {
            int idx = tid + it * 256;
            int row = idx >> 2, kg = idx & 3;
            cp_async16(dstb + sw_off(row, kg), Qb + (size_t)row * CC + kb * 32 + kg * 8);
        }
#pragma unroll
        for (int it = 0; it < 2; it++) {
            int idx = tid + it * 256;
            int row = idx >> 2, kg = idx & 3;
            cp_async16(dstb + 8192 + sw_off(row, kg), Kb + (size_t)row * CC + kb * 32 + kg * 8);
        }
        cp_commit();
    };

    load_stage(0, 0);
    load_stage(1, 1);

    const int KB = CC / 32;
    for (int kb = 0; kb < KB; kb++) {
        const int buf = kb % 3;
        if (kb < KB - 1) cp_wait<1>(); else cp_wait<0>();
        __syncthreads();
        if (kb + 2 < KB) load_stage(kb + 2, (kb + 2) % 3);

        const uint32_t stb = sbase + buf * 16384;
#pragma unroll
        for (int kh = 0; kh < 2; kh++) {
            uint32_t af[2][4], bf[4][4];
#pragma unroll
            for (int mt = 0; mt < 2; mt++)
                ldmatrix_x4(af[mt][0], af[mt][1], af[mt][2], af[mt][3],
                            stb + aoff[mt][kh]);
#pragma unroll
            for (int i = 0; i < 4; i++)
                ldmatrix_x4(bf[i][0], bf[i][1], bf[i][2], bf[i][3],
                            stb + boff[i][kh]);
#pragma unroll
            for (int mt = 0; mt < 2; mt++)
#pragma unroll
                for (int i = 0; i < 4; i++) {
                    mma_bf16(acc[mt][2*i][0], acc[mt][2*i][1], acc[mt][2*i][2], acc[mt][2*i][3],
                             af[mt][0], af[mt][1], af[mt][2], af[mt][3],
                             bf[i][0], bf[i][1]);
                    mma_bf16(acc[mt][2*i+1][0], acc[mt][2*i+1][1], acc[mt][2*i+1][2], acc[mt][2*i+1][3],
                             af[mt][0], af[mt][1], af[mt][2], af[mt][3],
                             bf[i][2], bf[i][3]);
                }
        }
    }

    __syncthreads();   // pipeline smem now reusable

    __nv_bfloat16* sE = (__nv_bfloat16*)smem;   // staged bf16 E tile [128][128]
    float* s_red = (float*)(smem + 32768);
    float* s_tm  = s_red + 256;
    float* s_l   = s_tm + 128;
    float* s_bc  = s_l + 256;

    if (tid < 128) s_bc[tid] = bcol[(size_t)bz * NN_ + n0 + tid];
    __syncthreads();

    const int grow = lid >> 2;
    const int gcol = (lid & 3) * 2;

    // Add column logit bias into acc (exact bias handling for bq)
#pragma unroll
    for (int mt = 0; mt < 2; mt++)
#pragma unroll
        for (int nt = 0; nt < 8; nt++) {
            const int cl = wn * 64 + nt * 8 + gcol;
            float b0 = s_bc[cl], b1 = s_bc[cl + 1];
            acc[mt][nt][0] += b0; acc[mt][nt][1] += b1;
            acc[mt][nt][2] += b0; acc[mt][nt][3] += b1;
        }

    // Sweep 1: per-thread row maxes over raw fp32 acc
    float pmax[2][2];
#pragma unroll
    for (int mt = 0; mt < 2; mt++) { pmax[mt][0] = -3.0e38f; pmax[mt][1] = -3.0e38f; }
#pragma unroll
    for (int mt = 0; mt < 2; mt++)
#pragma unroll
        for (int nt = 0; nt < 8; nt++) {
            pmax[mt][0] = fmaxf(pmax[mt][0], fmaxf(acc[mt][nt][0], acc[mt][nt][1]));
            pmax[mt][1] = fmaxf(pmax[mt][1], fmaxf(acc[mt][nt][2], acc[mt][nt][3]));
        }
#pragma unroll
    for (int mt = 0; mt < 2; mt++)
#pragma unroll
        for (int h = 0; h < 2; h++) {
            float v = pmax[mt][h];
            v = fmaxf(v, __shfl_xor_sync(0xffffffffu, v, 1));
            v = fmaxf(v, __shfl_xor_sync(0xffffffffu, v, 2));
            if ((lid & 3) == 0)
                s_red[(wm * 32 + mt * 16 + h * 8 + grow) * 2 + wn] = v;
        }
    __syncthreads();
    if (tid < 128) s_tm[tid] = fmaxf(s_red[tid * 2], s_red[tid * 2 + 1]);
    __syncthreads();

    // Sweep 2: E = bf16(exp(acc - tm)); stage in smem; psum from STORED values
    float psum[2][2] = {{0.0f, 0.0f}, {0.0f, 0.0f}};
#pragma unroll
    for (int mt = 0; mt < 2; mt++) {
        const int rl0 = wm * 32 + mt * 16 + grow;
        const float tm0 = s_tm[rl0];
        const float tm1 = s_tm[rl0 + 8];
#pragma unroll
        for (int nt = 0; nt < 8; nt++) {
            const int cl = wn * 64 + nt * 8 + gcol;
            float e00 = fexp(acc[mt][nt][0] - tm0), e01 = fexp(acc[mt][nt][1] - tm0);
            float e10 = fexp(acc[mt][nt][2] - tm1), e11 = fexp(acc[mt][nt][3] - tm1);
            __nv_bfloat162 h0 = __float22bfloat162_rn(make_float2(e00, e01));
            __nv_bfloat162 h1 = __float22bfloat162_rn(make_float2(e10, e11));
            *(__nv_bfloat162*)(sE + rl0 * 128 + cl) = h0;
            *(__nv_bfloat162*)(sE + (rl0 + 8) * 128 + cl) = h1;
            float2 f0 = __bfloat1622float2(h0);
            float2 f1 = __bfloat1622float2(h1);
            psum[mt][0] += f0.x + f0.y;
            psum[mt][1] += f1.x + f1.y;
        }
    }
#pragma unroll
    for (int mt = 0; mt < 2; mt++)
#pragma unroll
        for (int h = 0; h < 2; h++) {
            float v = psum[mt][h];
            v += __shfl_xor_sync(0xffffffffu, v, 1);
            v += __shfl_xor_sync(0xffffffffu, v, 2);
            if ((lid & 3) == 0)
                s_l[(wm * 32 + mt * 16 + h * 8 + grow) * 2 + wn] = v;
        }
    __syncthreads();

    // Coalesced E store
    {
        __nv_bfloat16* Eg = E + (size_t)bz * SBATCH + (size_t)m0 * NN_ + n0;
#pragma unroll
        for (int it = 0; it < 8; it++) {
            int c   = tid + it * 256;
            int row = c >> 4;
            int off = (c & 15) * 8;
            *(uint4*)(Eg + (size_t)row * NN_ + off) = *(uint4*)(sE + row * 128 + off);
        }
    }
    if (tid < 128) {
        const size_t brow = (size_t)bz * NN_ + m0 + tid;
        pm[(size_t)blockIdx.x * MM + brow] = s_tm[tid];
        pl[(size_t)blockIdx.x * MM + brow] = s_l[tid * 2] + s_l[tid * 2 + 1];
    }
}

// ---------------------------------------------------------------------------
// Generic mma GEMM (TERMS=1 bf16, TERMS=3 split-bf16).
// EPI 0: +bias -> bf16 out (smem-staged coalesced). EPI 1: +bias -> fp32 out.
// ---------------------------------------------------------------------------
template<int TERMS, int EPI>
__global__ void __launch_bounds__(256, 2)
mma_gemm_kernel(const __nv_bfloat16* __restrict__ Ah,
                const __nv_bfloat16* __restrict__ Al,
                const __nv_bfloat16* __restrict__ Bh,
                const __nv_bfloat16* __restrict__ Bl,
                void* __restrict__ Cout, int N, int K,
                const float* __restrict__ bias)
{
    constexpr int STAGE = (TERMS == 3) ? 32768 : 16384;
    constexpr uint32_t BOFF = (TERMS == 3) ? 16384u : 8192u;
    extern __shared__ __align__(1024) char smem[];
    const uint32_t sbase = smem_u32(smem);

    const int tid = threadIdx.x;
    const int wid = tid >> 5;
    const int lid = tid & 31;
    const int wm  = wid & 3;
    const int wn  = wid >> 2;
    const int n0  = blockIdx.x * 128;
    const int m0  = blockIdx.y * 128;

    const __nv_bfloat16* Ahb = Ah + (size_t)m0 * K;
    const __nv_bfloat16* Alb = (TERMS == 3) ? Al + (size_t)m0 * K : nullptr;
    const __nv_bfloat16* Bhb = Bh + (size_t)n0 * K;
    const __nv_bfloat16* Blb = (TERMS == 3) ? Bl + (size_t)n0 * K : nullptr;

    const int mgrp = lid >> 3;
    const int lr   = lid & 7;
    uint32_t aoff[2][2], boff[4][2];
#pragma unroll
    for (int mt = 0; mt < 2; mt++)
#pragma unroll
        for (int kh = 0; kh < 2; kh++) {
            int row = wm * 32 + mt * 16 + lr + ((mgrp & 1) << 3);
            int kg  = 2 * kh + (mgrp >> 1);
            aoff[mt][kh] = sw_off(row, kg);
        }
#pragma unroll
    for (int i = 0; i < 4; i++)
#pragma unroll
        for (int kh = 0; kh < 2; kh++) {
            int row = wn * 64 + i * 16 + lr + ((mgrp >> 1) << 3);
            int kg  = 2 * kh + (mgrp & 1);
            boff[i][kh] = BOFF + sw_off(row, kg);
        }

    float acc[2][8][4];
#pragma unroll
    for (int mt = 0; mt < 2; mt++)
#pragma unroll
        for (int nt = 0; nt < 8; nt++)
#pragma unroll
            for (int e = 0; e < 4; e++) acc[mt][nt][e] = 0.0f;

    auto load_stage = [&](int kb, int buf) {
        uint32_t dstb = sbase + buf * STAGE;
#pragma unroll
        for (int it = 0; it < 2; it++) {
            int idx = tid + it * 256;
            int row = idx >> 2, kg = idx & 3;
            size_t goff = (size_t)row * K + kb * 32 + kg * 8;
            uint32_t so = sw_off(row, kg);
            cp_async16(dstb + so, Ahb + goff);
            if (TERMS == 3) cp_async16(dstb + 8192u + so, Alb + goff);
            cp_async16(dstb + BOFF + so, Bhb + goff);
            if (TERMS == 3) cp_async16(dstb + BOFF + 8192u + so, Blb + goff);
        }
        cp_commit();
    };

    load_stage(0, 0);
    load_stage(1, 1);

    const int KB = K / 32;
    for (int kb = 0; kb < KB; kb++) {
        const int buf = kb % 3;
        if (kb < KB - 1) cp_wait<1>(); else cp_wait<0>();
        __syncthreads();
        if (kb + 2 < KB) load_stage(kb + 2, (kb + 2) % 3);

        const uint32_t stb = sbase + buf * STAGE;
#pragma unroll
        for (int kh = 0; kh < 2; kh++) {
            uint32_t afh[2][4], bfh[4][4];
            uint32_t afl[2][4], bfl[4][4];
#pragma unroll
            for (int mt = 0; mt < 2; mt++) {
                ldmatrix_x4(afh[mt][0], afh[mt][1], afh[mt][2], afh[mt][3],
                            stb + aoff[mt][kh]);
                if (TERMS == 3)
                    ldmatrix_x4(afl[mt][0], afl[mt][1], afl[mt][2], afl[mt][3],
                                stb + 8192u + aoff[mt][kh]);
            }
#pragma unroll
            for (int i = 0; i < 4; i++) {
                ldmatrix_x4(bfh[i][0], bfh[i][1], bfh[i][2], bfh[i][3],
                            stb + boff[i][kh]);
                if (TERMS == 3)
                    ldmatrix_x4(bfl[i][0], bfl[i][1], bfl[i][2], bfl[i][3],
                                stb + 8192u + boff[i][kh]);
            }
#pragma unroll
            for (int mt = 0; mt < 2; mt++)
#pragma unroll
                for (int i = 0; i < 4; i++) {
#pragma unroll
                    for (int h = 0; h < 2; h++) {
                        float* c0 = acc[mt][2*i + h];
                        mma_bf16(c0[0], c0[1], c0[2], c0[3],
                                 afh[mt][0], afh[mt][1], afh[mt][2], afh[mt][3],
                                 bfh[i][2*h], bfh[i][2*h + 1]);
                        if (TERMS == 3) {
                            mma_bf16(c0[0], c0[1], c0[2], c0[3],
                                     afh[mt][0], afh[mt][1], afh[mt][2], afh[mt][3],
                                     bfl[i][2*h], bfl[i][2*h + 1]);
                            mma_bf16(c0[0], c0[1], c0[2], c0[3],
                                     afl[mt][0], afl[mt][1], afl[mt][2], afl[mt][3],
                                     bfh[i][2*h], bfh[i][2*h + 1]);
                        }
                    }
                }
        }
    }

    const int grow = lid >> 2;
    const int gcol = (lid & 3) * 2;
    if (EPI == 0) {
        __syncthreads();
        __nv_bfloat16* sC = (__nv_bfloat16*)smem;
#pragma unroll
        for (int mt = 0; mt < 2; mt++) {
            const int rl0 = wm * 32 + mt * 16 + grow;
#pragma unroll
            for (int nt = 0; nt < 8; nt++) {
                const int cl  = wn * 64 + nt * 8 + gcol;
                const int col = n0 + cl;
                float b0 = bias[col], b1 = bias[col + 1];
                *(__nv_bfloat162*)(sC + rl0 * 128 + cl) = __float22bfloat162_rn(
                    make_float2(acc[mt][nt][0] + b0, acc[mt][nt][1] + b1));
                *(__nv_bfloat162*)(sC + (rl0 + 8) * 128 + cl) = __float22bfloat162_rn(
                    make_float2(acc[mt][nt][2] + b0, acc[mt][nt][3] + b1));
            }
        }
        __syncthreads();
        __nv_bfloat16* Cg = (__nv_bfloat16*)Cout + (size_t)m0 * N + n0;
#pragma unroll
        for (int it = 0; it < 8; it++) {
            int c   = tid + it * 256;
            int row = c >> 4;
            int off = (c & 15) * 8;
            *(uint4*)(Cg + (size_t)row * N + off) = *(uint4*)(sC + row * 128 + off);
        }
    } else {
#pragma unroll
        for (int mt = 0; mt < 2; mt++) {
#pragma unroll
            for (int nt = 0; nt < 8; nt++) {
                const int col  = n0 + wn * 64 + nt * 8 + gcol;
                const int rowa = m0 + wm * 32 + mt * 16 + grow;
                float b0 = bias[col], b1 = bias[col + 1];
                *(float2*)((float*)Cout + (size_t)rowa * N + col)
                    = make_float2(acc[mt][nt][0] + b0, acc[mt][nt][1] + b1);
                *(float2*)((float*)Cout + (size_t)(rowa + 8) * N + col)
                    = make_float2(acc[mt][nt][2] + b0, acc[mt][nt][3] + b1);
            }
        }
    }
}

// ---------------------------------------------------------------------------
// Small weight GEMM, k-split: part[kc][i][j] = sum_{c in chunk kc} R(i,c)*L(j,c)
// ---------------------------------------------------------------------------
template<bool TRANSR>
__global__ void __launch_bounds__(256)
smallgemm_split_kernel(const float* __restrict__ R, const float* __restrict__ L,
                       float* __restrict__ part)
{
    __shared__ float Rs[32][64];
    __shared__ float Ls[32][64];
    const int tid = threadIdx.x;
    const int i0 = blockIdx.x * 64, j0 = blockIdx.y * 64;
    const int kc = blockIdx.z;
    const int tx = tid & 15, ty = tid >> 4;
    constexpr int KCH = CC / KSP;   // 32

    float acc[4][4];
#pragma unroll
    for (int a = 0; a < 4; a++)
#pragma unroll
        for (int b = 0; b < 4; b++) acc[a][b] = 0.0f;

    for (int c0 = kc * KCH; c0 < kc * KCH + KCH; c0 += 32) {
        if (!TRANSR) {
            int i = tid >> 2, cb = (tid & 3) * 8;
            float4 a = *(const float4*)(R + (size_t)(i0 + i) * CC + c0 + cb);
            float4 b = *(const float4*)(R + (size_t)(i0 + i) * CC + c0 + cb + 4);
            Rs[cb+0][i] = a.x; Rs[cb+1][i] = a.y; Rs[cb+2][i] = a.z; Rs[cb+3][i] = a.w;
            Rs[cb+4][i] = b.x; Rs[cb+5][i] = b.y; Rs[cb+6][i] = b.z; Rs[cb+7][i] = b.w;
        } else {
            int c = tid >> 3, ib = (tid & 7) * 8;
            float4 a = *(const float4*)(R + (size_t)(c0 + c) * CC + i0 + ib);
            float4 b = *(const float4*)(R + (size_t)(c0 + c) * CC + i0 + ib + 4);
            Rs[c][ib+0] = a.x; Rs[c][ib+1] = a.y; Rs[c][ib+2] = a.z; Rs[c][ib+3] = a.w;
            Rs[c][ib+4] = b.x; Rs[c][ib+5] = b.y; Rs[c][ib+6] = b.z; Rs[c][ib+7] = b.w;
        }
        {
            int j = tid >> 2, cb = (tid & 3) * 8;
            float4 a = *(const float4*)(L + (size_t)(j0 + j) * CC + c0 + cb);
            float4 b = *(const float4*)(L + (size_t)(j0 + j) * CC + c0 + cb + 4);
            Ls[cb+0][j] = a.x; Ls[cb+1][j] = a.y; Ls[cb+2][j] = a.z; Ls[cb+3][j] = a.w;
            Ls[cb+4][j] = b.x; Ls[cb+5][j] = b.y; Ls[cb+6][j] = b.z; Ls[cb+7][j] = b.w;
        }
        __syncthreads();
#pragma unroll
        for (int c = 0; c < 32; c++) {
            float ri[4], lj[4];
#pragma unroll
            for (int a = 0; a < 4; a++) ri[a] = Rs[c][ty * 4 + a];
#pragma unroll
            for (int b = 0; b < 4; b++) lj[b] = Ls[c][tx * 4 + b];
#pragma unroll
            for (int a = 0; a < 4; a++)
#pragma unroll
                for (int b = 0; b < 4; b++)
                    acc[a][b] = fmaf(ri[a], lj[b], acc[a][b]);
        }
        __syncthreads();
    }

    float* pb = part + (size_t)kc * CC * CC;
#pragma unroll
    for (int a = 0; a < 4; a++)
#pragma unroll
        for (int b = 0; b < 4; b++)
            pb[(size_t)(i0 + ty * 4 + a) * CC + j0 + tx * 4 + b] = acc[a][b];
}

// Combine KSP k-split partials -> bf16 hi (+lo). 4 elems/thread.
template<bool WRITE_LO>
__global__ void __launch_bounds__(256)
wcombine_kernel(const float* __restrict__ part,
                __nv_bfloat16* __restrict__ Ch, __nv_bfloat16* __restrict__ Cl)
{
    size_t i = ((size_t)blockIdx.x * 256 + threadIdx.x) * 4;
    float4 s = make_float4(0.f, 0.f, 0.f, 0.f);
#pragma unroll
    for (int p = 0; p < KSP; p++) {
        float4 v = *(const float4*)(part + (size_t)p * CC * CC + i);
        s.x += v.x; s.y += v.y; s.z += v.z; s.w += v.w;
    }
    __nv_bfloat16 h0 = __float2bfloat16(s.x), h1 = __float2bfloat16(s.y);
    __nv_bfloat16 h2 = __float2bfloat16(s.z), h3 = __float2bfloat16(s.w);
    __nv_bfloat162 hp[2] = {{h0, h1}, {h2, h3}};
    *(uint2*)(Ch + i) = *(uint2*)hp;
    if (WRITE_LO) {
        __nv_bfloat162 lp[2] = {
            {__float2bfloat16(s.x - __bfloat162float(h0)),
             __float2bfloat16(s.y - __bfloat162float(h1))},
            {__float2bfloat16(s.z - __bfloat162float(h2)),
             __float2bfloat16(s.w - __bfloat162float(h3))}};
        *(uint2*)(Cl + i) = *(uint2*)lp;
    }
}

// ---------------------------------------------------------------------------
// wkbq[r] = Wk[r,:] . bq   (warp per row, coalesced, bq in smem)
// ---------------------------------------------------------------------------
__global__ void __launch_bounds__(256)
wkbq_kernel(const float* __restrict__ Wk, const float* __restrict__ bq,
            float* __restrict__ wkbq)
{
    __shared__ float b[CC];
    for (int i = threadIdx.x; i < CC; i += 256) b[i] = bq[i];
    __syncthreads();
    const int warp = threadIdx.x >> 5, lane = threadIdx.x & 31;
    const int r = blockIdx.x * 8 + warp;
    const float* Wr = Wk + (size_t)r * CC;
    float acc = 0.0f;
#pragma unroll
    for (int c = lane * 4; c < CC; c += 128) {
        float4 v = *(const float4*)(Wr + c);
        acc += v.x * b[c] + v.y * b[c+1] + v.z * b[c+2] + v.w * b[c+3];
    }
#pragma unroll
    for (int o = 16; o > 0; o >>= 1) acc += __shfl_xor_sync(0xffffffffu, acc, o);
    if (lane == 0) wkbq[r] = acc;
}

// bv2[t] = sum_c bv[c] * Wo[c, t]  (coalesced in t)
__global__ void __launch_bounds__(512)
bv2_kernel(const float* __restrict__ Wo, const float* __restrict__ bv,
           float* __restrict__ bv2)
{
    __shared__ float b[CC];
    for (int i = threadIdx.x; i < CC; i += 512) b[i] = bv[i];
    __syncthreads();
    const int t = threadIdx.x;
    float acc = 0.0f;
    for (int c = 0; c < CC; c++) acc += b[c] * Wo[(size_t)c * CC + t];
    bv2[t] = acc;
}

// bcol[r] = x_r . wkbq  (warp per row)
__global__ void __launch_bounds__(256)
bcol_kernel(const float* __restrict__ x, const float* __restrict__ wkbq,
            float* __restrict__ bcol)
{
    __shared__ float w[CC];
    for (int i = threadIdx.x; i < CC; i += 256) w[i] = wkbq[i];
    __syncthreads();
    const int warp = threadIdx.x >> 5, lane = threadIdx.x & 31;
    const int r = blockIdx.x * 8 + warp;
    const float* xr = x + (size_t)r * CC;
    float acc = 0.0f;
#pragma unroll
    for (int c = lane * 4; c < CC; c += 128) {
        float4 v = *(const float4*)(xr + c);
        acc += v.x * w[c] + v.y * w[c+1] + v.z * w[c+2] + v.w * w[c+3];
    }
#pragma unroll
    for (int o = 16; o > 0; o >>= 1) acc += __shfl_xor_sync(0xffffffffu, acc, o);
    if (lane == 0) bcol[r] = acc;
}

// split fp32 -> bf16 hi/lo
__global__ void __launch_bounds__(256)
split_kernel(const float* __restrict__ x,
             __nv_bfloat16* __restrict__ xh, __nv_bfloat16* __restrict__ xl)
{
    size_t i = ((size_t)blockIdx.x * 256 + threadIdx.x) * 4;
    float4 v = *(const float4*)(x + i);
    __nv_bfloat16 h0 = __float2bfloat16(v.x), h1 = __float2bfloat16(v.y);
    __nv_bfloat16 h2 = __float2bfloat16(v.z), h3 = __float2bfloat16(v.w);
    __nv_bfloat16 l0 = __float2bfloat16(v.x - __bfloat162float(h0));
    __nv_bfloat16 l1 = __float2bfloat16(v.y - __bfloat162float(h1));
    __nv_bfloat16 l2 = __float2bfloat16(v.z - __bfloat162float(h2));
    __nv_bfloat16 l3 = __float2bfloat16(v.w - __bfloat162float(h3));
    __nv_bfloat162 hp[2] = {{h0, h1}, {h2, h3}};
    __nv_bfloat162 lp[2] = {{l0, l1}, {l2, l3}};
    *(uint2*)(xh + i) = *(uint2*)hp;
    *(uint2*)(xl + i) = *(uint2*)lp;
}

// ---------------------------------------------------------------------------
// Column sums over stored E: c[n] = sum_m E[m,n] * w[m],
// w[m] = exp(pm[nt][m] - M_m) * invL_m  (no exp in the inner loop).
// Block: 1024 columns (8 n-tiles; one warp per n-tile), 128 m-rows.
// ---------------------------------------------------------------------------
__global__ void __launch_bounds__(256)
colsum_part_kernel(const __nv_bfloat16* __restrict__ E,
                   const float* __restrict__ pm,
                   const float* __restrict__ pl,
                   float* __restrict__ cpart)
{
    __shared__ float sm[128], si[128];
    __shared__ float swt[8 * 128];
    const int b     = blockIdx.z;
    const int n     = blockIdx.x * 1024 + threadIdx.x * 4;
    const int m0    = blockIdx.y * 128;
    const int rbase = b * 4096;
    if (threadIdx.x < 128) {
        const int r = rbase + m0 + threadIdx.x;
        float M = -3.0e38f;
#pragma unroll
        for (int t = 0; t < 32; t++) M = fmaxf(M, pm[(size_t)t * MM + r]);
        float L = 0.0f;
#pragma unroll
        for (int t = 0; t < 32; t++)
            L += pl[(size_t)t * MM + r] * fexp(pm[(size_t)t * MM + r] - M);
        sm[threadIdx.x] = M;
        si[threadIdx.x] = 1.0f / L;
    }
    __syncthreads();

    // Per-warp weight table: warp w owns n-tile nt = bx*8 + w.
    const int warp = threadIdx.x >> 5, lane = threadIdx.x & 31;
    const int nt   = blockIdx.x * 8 + warp;
    for (int m = lane; m < 128; m += 32) {
        const int r = rbase + m0 + m;
        swt[warp * 128 + m] = fexp(pm[(size_t)nt * MM + r] - sm[m]) * si[m];
    }
    __syncthreads();

    const float* w = swt + warp * 128;
    const __nv_bfloat16* Eb = E + (size_t)b * SBATCH + (size_t)m0 * 4096 + n;
    float a0 = 0.0f, a1 = 0.0f, a2 = 0.0f, a3 = 0.0f;
#pragma unroll 4
    for (int mm = 0; mm < 128; mm++) {
        uint2 u = *(const uint2*)(Eb + (size_t)mm * 4096);
        float2 f0 = __bfloat1622float2(reinterpret_cast<__nv_bfloat162&>(u.x));
        float2 f1 = __bfloat1622float2(reinterpret_cast<__nv_bfloat162&>(u.y));
        float wm = w[mm];
        a0 = fmaf(f0.x, wm, a0);
        a1 = fmaf(f0.y, wm, a1);
        a2 = fmaf(f1.x, wm, a2);
        a3 = fmaf(f1.y, wm, a3);
    }
    *(float4*)(cpart + (size_t)blockIdx.y * MM + rbase + n)
        = make_float4(a0, a1, a2, a3);
}

__global__ void __launch_bounds__(256)
colsum_final_kernel(const float* __restrict__ cpart, float* __restrict__ srow)
{
    const int i = blockIdx.x * 256 + threadIdx.x;
    float c = 0.0f;
#pragma unroll
    for (int p = 0; p < 32; p++) c += cpart[(size_t)p * MM + i];
    srow[i] = c / (c + 1e-9f);
}

// ---------------------------------------------------------------------------
// Final elementwise epilogue: out = relu(BN(s[r]*P + bo)) + x
// ---------------------------------------------------------------------------
__global__ void __launch_bounds__(256)
final_epi_kernel(const float* __restrict__ P, const float* __restrict__ srow,
                 const float* __restrict__ x, const float* __restrict__ bo,
                 const float* __restrict__ bns, const float* __restrict__ bnb,
                 const float* __restrict__ bnm, const float* __restrict__ bnv,
                 float* __restrict__ out)
{
    size_t i = ((size_t)blockIdx.x * 256 + threadIdx.x) * 4;
    const int r = (int)(i >> 9);
    const int c = (int)(i & 511);
    const float s = srow[r];
    float4 p = *(const float4*)(P + i);
    float4 xr = *(const float4*)(x + i);
    float pv[4] = {p.x, p.y, p.z, p.w};
    float xv[4] = {xr.x, xr.y, xr.z, xr.w};
    float o[4];
#pragma unroll
    for (int j = 0; j < 4; j++) {
        const int cc = c + j;
        float g = rsqrtf(bnv[cc] + 1e-5f) * bns[cc];
        float v = s * pv[j] + bo[cc];
        v = (v - bnm[cc]) * g + bnb[cc];
        o[j] = fmaxf(v, 0.0f) + xv[j];
    }
    *(float4*)(out + i) = make_float4(o[0], o[1], o[2], o[3]);
}

// ---------------------------------------------------------------------------
extern "C" void kernel_launch(void* const* d_in, const int* in_sizes, int n_in,
                              void* d_out, int out_size)
{
    // metadata order: inputs, Wq, Wk, Wv, Wo, bq, bk, bv, bo, bn_* (two loops!)
    const float* x   = (const float*)d_in[0];
    const float* Wq  = (const float*)d_in[1];
    const float* Wk  = (const float*)d_in[2];
    const float* Wv  = (const float*)d_in[3];
    const float* Wo  = (const float*)d_in[4];
    const float* bq  = (const float*)d_in[5];
    // bk (d_in[6]) only contributes row-constant logit terms -> cancels in softmax.
    const float* bv  = (const float*)d_in[7];
    const float* bo  = (const float*)d_in[8];
    const float* bns = (const float*)d_in[9];
    const float* bnb = (const float*)d_in[10];
    const float* bnm = (const float*)d_in[11];
    const float* bnv = (const float*)d_in[12];
    float* out = (float*)d_out;

    void *xh, *xl, *qh, *P, *E, *qkT, *w2h, *w2l, *part1, *part2;
    void *wkbq, *bv2, *bcol, *zero, *pm, *pl, *cpart, *srow;
    cudaGetSymbolAddress(&xh,   g_xh);   cudaGetSymbolAddress(&xl,   g_xl);
    cudaGetSymbolAddress(&qh,   g_qh);   cudaGetSymbolAddress(&P,    g_P);
    cudaGetSymbolAddress(&E,    g_E);
    cudaGetSymbolAddress(&qkT,  g_qkT);
    cudaGetSymbolAddress(&w2h,  g_w2h);  cudaGetSymbolAddress(&w2l,  g_w2l);
    cudaGetSymbolAddress(&part1, g_part1);
    cudaGetSymbolAddress(&part2, g_part2);
    cudaGetSymbolAddress(&wkbq, g_wkbq); cudaGetSymbolAddress(&bv2,  g_bv2);
    cudaGetSymbolAddress(&bcol, g_bcol); cudaGetSymbolAddress(&zero, g_zero);
    cudaGetSymbolAddress(&pm,    g_pm);
    cudaGetSymbolAddress(&pl,    g_pl);
    cudaGetSymbolAddress(&cpart, g_cpart);
    cudaGetSymbolAddress(&srow,  g_srow);

    static cudaStream_t s2 = nullptr;
    static cudaEvent_t  eFork = nullptr, eQk = nullptr, eBcol = nullptr,
                        eP = nullptr, eSplit = nullptr;
    if (s2 == nullptr) {
        cudaStreamCreateWithFlags(&s2, cudaStreamNonBlocking);
        cudaEventCreateWithFlags(&eFork, cudaEventDisableTiming);
        cudaEventCreateWithFlags(&eQk, cudaEventDisableTiming);
        cudaEventCreateWithFlags(&eBcol, cudaEventDisableTiming);
        cudaEventCreateWithFlags(&eP, cudaEventDisableTiming);
        cudaEventCreateWithFlags(&eSplit, cudaEventDisableTiming);
        cudaFuncSetAttribute(mma_gemm_kernel<1, 0>,
            cudaFuncAttributeMaxDynamicSharedMemorySize, 49152);
        cudaFuncSetAttribute(mma_gemm_kernel<3, 1>,
            cudaFuncAttributeMaxDynamicSharedMemorySize, 98304);
    }

    dim3 blk(256);
    dim3 gProj(CC / 128, MM / 128);           // (4, 64)

    // Fork s2 at t=0: everything on s2 depends only on harness inputs.
    cudaEventRecord(eFork, 0);
    cudaStreamWaitEvent(s2, eFork, 0);

    // main: split x into bf16 hi/lo (concurrent with s2 prep)
    split_kernel<<<(MM * CC) / 1024, blk>>>(x, (__nv_bfloat16*)xh, (__nv_bfloat16*)xl);
    cudaEventRecord(eSplit, 0);

    // s2: qkT chain FIRST (it gates q' on main), bcol deferred after eQk.
    wkbq_kernel<<<CC / 8, blk, 0, s2>>>(Wk, bq, (float*)wkbq);
    smallgemm_split_kernel<false><<<dim3(8, 8, KSP), blk, 0, s2>>>(
        Wk, Wq, (float*)part1);
    wcombine_kernel<false><<<(CC * CC) / 1024, blk, 0, s2>>>(
        (const float*)part1, (__nv_bfloat16*)qkT, nullptr);
    cudaEventRecord(eQk, s2);
    // bcol hides under q' on main.
    bcol_kernel<<<MM / 8, blk, 0, s2>>>(x, (const float*)wkbq, (float*)bcol);
    cudaEventRecord(eBcol, s2);
    // W2 chain + P GEMM (overlaps K2 on main)
    bv2_kernel<<<1, 512, 0, s2>>>(Wo, bv, (float*)bv2);
    smallgemm_split_kernel<true><<<dim3(8, 8, KSP), blk, 0, s2>>>(
        Wo, Wv, (float*)part2);
    wcombine_kernel<true><<<(CC * CC) / 1024, blk, 0, s2>>>(
        (const float*)part2, (__nv_bfloat16*)w2h, (__nv_bfloat16*)w2l);
    cudaStreamWaitEvent(s2, eSplit, 0);
    mma_gemm_kernel<3, 1><<<gProj, blk, 98304, s2>>>(
        (const __nv_bfloat16*)xh, (const __nv_bfloat16*)xl,
        (const __nv_bfloat16*)w2h, (const __nv_bfloat16*)w2l,
        P, CC, CC, (const float*)bv2);
    cudaEventRecord(eP, s2);

    // main: q' = x @ Wqk (needs qkT from s2)
    cudaStreamWaitEvent(0, eQk, 0);
    mma_gemm_kernel<1, 0><<<gProj, blk, 49152>>>(
        (const __nv_bfloat16*)xh, nullptr, (const __nv_bfloat16*)qkT, nullptr,
        qh, CC, CC, (const float*)zero);

    // K2: E = bf16(exp(q'@x^T + bcol - tilemax)), fused per-tile stats
    cudaStreamWaitEvent(0, eBcol, 0);
    qk_mma_kernel<<<dim3(32, 32, 2), blk>>>(
        (const __nv_bfloat16*)qh, (const __nv_bfloat16*)xh, (__nv_bfloat16*)E,
        (float*)pm, (float*)pl, (const float*)bcol);

    // colsum -> s[n]  (pure weighted sum over stored E)
    colsum_part_kernel<<<dim3(4, 32, 2), blk>>>((const __nv_bfloat16*)E,
        (const float*)pm, (const float*)pl, (float*)cpart);
    colsum_final_kernel<<<MM / 256, blk>>>((const float*)cpart, (float*)srow);

    // final: out = relu(BN(s[r]*P + bo)) + x   (needs P from s2)
    cudaStreamWaitEvent(0, eP, 0);
    final_epi_kernel<<<(MM * CC) / 1024, blk>>>(
        (const float*)P, (const float*)srow, x, bo, bns, bnb, bnm, bnv, out);
}